// round 1
// baseline (speedup 1.0000x reference)
#include <cuda_runtime.h>
#include <math.h>

// Problem constants
#define B_    4
#define N_    16384
#define D_    256
#define H_    8
#define DH_   64
#define G_    64
#define INNER_ 512
#define BH_   32           // B_*H_
#define M_    65536        // B_*N_

typedef unsigned long long ull;

// ---- scratch (device globals: allocation-free per harness rules) ----
__device__ float g_xmid  [(size_t)BH_ * N_ * DH_];   // [B,H,N,DH]  134MB
__device__ float g_slicew[(size_t)BH_ * N_ * G_];    // [B,H,N,G]   134MB
__device__ float g_outx  [(size_t)M_ * INNER_];      // [B,N,H,DH]  134MB (token-major)
__device__ float g_norm  [BH_ * G_];
__device__ float g_tok   [BH_ * G_ * DH_];
__device__ float g_outs  [BH_ * G_ * DH_];

// ---- packed fp32x2 helpers (Blackwell FFMA2 path) ----
__device__ __forceinline__ ull pk2(float lo, float hi) {
    ull r; asm("mov.b64 %0, {%1,%2};" : "=l"(r) : "f"(lo), "f"(hi)); return r;
}
__device__ __forceinline__ void fma2(ull& d, ull a, ull b) {
    asm("fma.rn.f32x2 %0, %1, %2, %0;" : "+l"(d) : "l"(a), "l"(b));
}
__device__ __forceinline__ float2 up2(ull v) {
    float2 r; asm("mov.b64 {%0,%1}, %2;" : "=f"(r.x), "=f"(r.y) : "l"(v)); return r;
}
__device__ __forceinline__ float gelu_f(float x) {
    return 0.5f * x * (1.0f + erff(x * 0.70710678118654752f));
}

// ============================================================
// Zero the atomic accumulators (runs every replay: determinism)
// ============================================================
__global__ void k_zero() {
    int i = blockIdx.x * 256 + threadIdx.x;
    if (i < BH_ * G_)        g_norm[i] = 0.f;
    if (i < BH_ * G_ * DH_)  g_tok[i]  = 0.f;
}

// ============================================================
// SGEMM  C[M x NOUT] = A[M x K] @ W[NOUT x K]^T + bias
// 128x128 block tile, BK=16, 256 threads, 8x8 per thread,
// f32x2-packed accumulators (pairs along n).
// SCATTER=true: write to g_xmid in [B,H,N,DH] layout.
// ============================================================
template<int K, int NOUT, bool SCATTER>
__global__ void __launch_bounds__(256) k_gemm(const float* __restrict__ A,
                                              const float* __restrict__ W,
                                              const float* __restrict__ bias,
                                              float* __restrict__ C)
{
    __shared__ __align__(16) float As[16][132];
    __shared__ __align__(16) float Bs[16][132];
    const int t   = threadIdx.x;
    const int gm0 = blockIdx.y << 7;
    const int gn0 = blockIdx.x << 7;
    const int m0  = (t >> 4) << 3;
    const int n0  = (t & 15) << 3;

    ull acc[8][4];
#pragma unroll
    for (int i = 0; i < 8; ++i)
#pragma unroll
        for (int j = 0; j < 4; ++j) acc[i][j] = 0ull;

    const int r0 = t >> 2;
    const int kc = (t & 3) << 2;

    for (int k0 = 0; k0 < K; k0 += 16) {
#pragma unroll
        for (int it = 0; it < 2; ++it) {
            int r = r0 + (it << 6);
            float4 av = *(const float4*)(A + (size_t)(gm0 + r) * K + k0 + kc);
            As[kc + 0][r] = av.x; As[kc + 1][r] = av.y;
            As[kc + 2][r] = av.z; As[kc + 3][r] = av.w;
            float4 wv = *(const float4*)(W + (size_t)(gn0 + r) * K + k0 + kc);
            Bs[kc + 0][r] = wv.x; Bs[kc + 1][r] = wv.y;
            Bs[kc + 2][r] = wv.z; Bs[kc + 3][r] = wv.w;
        }
        __syncthreads();
#pragma unroll
        for (int kk = 0; kk < 16; ++kk) {
            float4 b0 = *(const float4*)&Bs[kk][n0];
            float4 b1 = *(const float4*)&Bs[kk][n0 + 4];
            ull bp[4] = { pk2(b0.x, b0.y), pk2(b0.z, b0.w),
                          pk2(b1.x, b1.y), pk2(b1.z, b1.w) };
            float4 a0 = *(const float4*)&As[kk][m0];
            float4 a1 = *(const float4*)&As[kk][m0 + 4];
            float am[8] = {a0.x, a0.y, a0.z, a0.w, a1.x, a1.y, a1.z, a1.w};
#pragma unroll
            for (int i = 0; i < 8; ++i) {
                ull as_ = pk2(am[i], am[i]);
#pragma unroll
                for (int j = 0; j < 4; ++j) fma2(acc[i][j], as_, bp[j]);
            }
        }
        __syncthreads();
    }

    float bv[8];
#pragma unroll
    for (int j = 0; j < 8; ++j) bv[j] = bias[gn0 + n0 + j];

#pragma unroll
    for (int i = 0; i < 8; ++i) {
        float o[8];
#pragma unroll
        for (int j = 0; j < 4; ++j) {
            float2 p = up2(acc[i][j]);
            o[2 * j]     = p.x + bv[2 * j];
            o[2 * j + 1] = p.y + bv[2 * j + 1];
        }
        int m = gm0 + m0 + i;
        float4 v0 = make_float4(o[0], o[1], o[2], o[3]);
        float4 v1 = make_float4(o[4], o[5], o[6], o[7]);
        if (SCATTER) {
            int b = m >> 14, n = m & (N_ - 1);
            int col = gn0 + n0;                 // 8 cols always within one head
            int h = col >> 6, c0 = col & 63;
            float* dst = g_xmid + (((size_t)(b * H_ + h) * N_ + n) * DH_ + c0);
            *(float4*)dst = v0; *(float4*)(dst + 4) = v1;
        } else {
            float* dst = C + (size_t)m * NOUT + gn0 + n0;
            *(float4*)dst = v0; *(float4*)(dst + 4) = v1;
        }
    }
}

// ============================================================
// Routing: per (b,h,token): temp MLP, gumbel-softmax slice
// weights -> g_slicew, per-g norm accumulated via atomics.
// Warp-per-token; lane owns g=lane and g=lane+32.
// ============================================================
__global__ void __launch_bounds__(256) k_route(const float* __restrict__ u,
    const float* __restrict__ W1, const float* __restrict__ b1,
    const float* __restrict__ W2, const float* __restrict__ b2,
    const float* __restrict__ biasH, const float* __restrict__ Ws,
    const float* __restrict__ bs)
{
    __shared__ float2 Wls[4096];            // interleaved {W1^T, Ws^T}
    __shared__ float  W2s[64], b1s[64], bss[64];
    __shared__ float  xms[8][64];

    int bh = blockIdx.x, chunk = blockIdx.y;
    int tid = threadIdx.x, w = tid >> 5, lane = tid & 31;

    for (int i = tid; i < 4096; i += 256) {
        int g = i >> 6, c = i & 63;
        Wls[c * 64 + g] = make_float2(W1[i], Ws[i]);   // W1[g][c], Ws[g][c]
    }
    if (tid < 64) { W2s[tid] = W2[tid]; b1s[tid] = b1[tid]; bss[tid] = bs[tid]; }
    __syncthreads();

    float biasv = biasH[bh & 7];
    float b2v   = b2[0];
    size_t base = (size_t)bh * N_ * 64;
    float n0acc = 0.f, n1acc = 0.f;
    int tok0 = chunk * 1024 + w * 128;

    for (int tt = 0; tt < 128; ++tt) {
        int n = tok0 + tt;
        size_t off = base + (size_t)n * 64;
        float x0 = g_xmid[off + lane], x1 = g_xmid[off + lane + 32];
        xms[w][lane] = x0; xms[w][lane + 32] = x1;
        __syncwarp();

        float t0 = b1s[lane], t1v = b1s[lane + 32];
        float l0 = bss[lane], l1  = bss[lane + 32];
#pragma unroll
        for (int c = 0; c < 64; ++c) {
            float xv = xms[w][c];
            float2 w0v = Wls[c * 64 + lane];
            float2 w1v = Wls[c * 64 + lane + 32];
            t0  += xv * w0v.x;  l0 += xv * w0v.y;
            t1v += xv * w1v.x;  l1 += xv * w1v.y;
        }
        __syncwarp();

        t0 = gelu_f(t0); t1v = gelu_f(t1v);
        float part = t0 * W2s[lane] + t1v * W2s[lane + 32];
#pragma unroll
        for (int o = 16; o; o >>= 1) part += __shfl_xor_sync(0xffffffffu, part, o);
        float temp = fmaxf(gelu_f(part + b2v) + biasv, 0.01f);

        float uu0 = u[off + lane], uu1 = u[off + lane + 32];
        float gn0 = -logf(-logf(uu0 + 1e-8f) + 1e-8f);
        float gn1 = -logf(-logf(uu1 + 1e-8f) + 1e-8f);
        float it  = 1.f / temp;
        float z0 = (l0 + gn0) * it, z1 = (l1 + gn1) * it;

        float mx = fmaxf(z0, z1);
#pragma unroll
        for (int o = 16; o; o >>= 1) mx = fmaxf(mx, __shfl_xor_sync(0xffffffffu, mx, o));
        float e0 = expf(z0 - mx), e1 = expf(z1 - mx);
        float s = e0 + e1;
#pragma unroll
        for (int o = 16; o; o >>= 1) s += __shfl_xor_sync(0xffffffffu, s, o);
        float inv = 1.f / s;
        float w0 = e0 * inv, w1 = e1 * inv;

        g_slicew[off + lane] = w0; g_slicew[off + lane + 32] = w1;
        n0acc += w0; n1acc += w1;
    }
    atomicAdd(&g_norm[bh * 64 + lane],      n0acc);
    atomicAdd(&g_norm[bh * 64 + lane + 32], n1acc);
}

// ============================================================
// Pooling: tok[bh][g][c] = sum_n slicew[bh][n][g]*xmid[bh][n][c]
// split-K over token chunks, atomicAdd reduction.
// ============================================================
__global__ void __launch_bounds__(256) k_pool()
{
    __shared__ __align__(16) float Xs[64][64];
    __shared__ __align__(16) float Wp[64][64];
    int bh = blockIdx.x, chunk = blockIdx.y;   // 8 chunks * 2048 tokens
    int tid = threadIdx.x;
    int c0 = (tid & 15) << 2;
    int g0 = (tid >> 4) << 2;
    float acc[4][4] = {};
    size_t base = (size_t)bh * N_ * 64 + (size_t)chunk * 2048 * 64;

    for (int t0 = 0; t0 < 2048; t0 += 64) {
#pragma unroll
        for (int it = 0; it < 4; ++it) {
            int v = tid + (it << 8);
            int rr = v >> 4, cc = (v & 15) << 2;
            *(float4*)&Xs[rr][cc] = *(const float4*)&g_xmid  [base + (size_t)(t0 + rr) * 64 + cc];
            *(float4*)&Wp[rr][cc] = *(const float4*)&g_slicew[base + (size_t)(t0 + rr) * 64 + cc];
        }
        __syncthreads();
#pragma unroll
        for (int tt2 = 0; tt2 < 64; ++tt2) {
            float4 xv = *(const float4*)&Xs[tt2][c0];
            float4 wv = *(const float4*)&Wp[tt2][g0];
            float xa[4] = {xv.x, xv.y, xv.z, xv.w};
            float wa[4] = {wv.x, wv.y, wv.z, wv.w};
#pragma unroll
            for (int j = 0; j < 4; ++j)
#pragma unroll
                for (int i = 0; i < 4; ++i) acc[j][i] += wa[j] * xa[i];
        }
        __syncthreads();
    }
#pragma unroll
    for (int j = 0; j < 4; ++j)
#pragma unroll
        for (int i = 0; i < 4; ++i)
            atomicAdd(&g_tok[bh * 4096 + (g0 + j) * 64 + (c0 + i)], acc[j][i]);
}

// ============================================================
// Slice attention over G=64 tokens per (b,h). One block per bh,
// thread = g row. V never materialized: out = (p @ T) @ Wv^T.
// ============================================================
__global__ void __launch_bounds__(64) k_attn(const float* __restrict__ Wq,
                                             const float* __restrict__ Wk,
                                             const float* __restrict__ Wv)
{
    __shared__ float T [64 * 65];
    __shared__ float Ks[64 * 64];
    int bh = blockIdx.x, tid = threadIdx.x;

    for (int i = tid; i < 4096; i += 64) {
        int g = i >> 6, c = i & 63;
        T[g * 65 + c] = g_tok[bh * 4096 + i] / (g_norm[bh * 64 + g] + 1e-5f);
    }
    __syncthreads();

    int g = tid;
    float q[64];
    for (int c = 0; c < 64; ++c) {
        float s0 = 0.f, s1 = 0.f;
        for (int k = 0; k < 64; k += 2) {
            s0 += T[g * 65 + k]     * Wq[c * 64 + k];
            s1 += T[g * 65 + k + 1] * Wq[c * 64 + k + 1];
        }
        q[c] = s0 + s1;
    }
    for (int c = 0; c < 64; ++c) {
        float s0 = 0.f, s1 = 0.f;
        for (int k = 0; k < 64; k += 2) {
            s0 += T[g * 65 + k]     * Wk[c * 64 + k];
            s1 += T[g * 65 + k + 1] * Wk[c * 64 + k + 1];
        }
        Ks[g * 64 + c] = s0 + s1;
    }
    __syncthreads();

    float sc[64];
    for (int j = 0; j < 64; ++j) {
        float s0 = 0.f, s1 = 0.f;
        for (int c = 0; c < 64; c += 2) {
            s0 += q[c]     * Ks[j * 64 + c];
            s1 += q[c + 1] * Ks[j * 64 + c + 1];
        }
        sc[j] = (s0 + s1) * 0.125f;   // 1/sqrt(64)
    }
    float mx = -1e30f;
    for (int j = 0; j < 64; ++j) mx = fmaxf(mx, sc[j]);
    float sum = 0.f;
    for (int j = 0; j < 64; ++j) { sc[j] = expf(sc[j] - mx); sum += sc[j]; }
    float inv = 1.f / sum;

    float pv[64];
    for (int c = 0; c < 64; ++c) {
        float s0 = 0.f, s1 = 0.f;
        for (int j = 0; j < 64; j += 2) {
            s0 += sc[j]     * T[j * 65 + c];
            s1 += sc[j + 1] * T[(j + 1) * 65 + c];
        }
        pv[c] = (s0 + s1) * inv;
    }
    for (int c = 0; c < 64; ++c) {
        float s0 = 0.f, s1 = 0.f;
        for (int k = 0; k < 64; k += 2) {
            s0 += pv[k]     * Wv[c * 64 + k];
            s1 += pv[k + 1] * Wv[c * 64 + k + 1];
        }
        g_outs[bh * 4096 + g * 64 + c] = s0 + s1;
    }
}

// ============================================================
// Scatter: out_x[b,n,h,c] = sum_g outs[bh][g][c]*slicew[bh][n][g]
// Token-major output so the final GEMM reads contiguous rows.
// ============================================================
__global__ void __launch_bounds__(256) k_scatter()
{
    __shared__ __align__(16) float Ss[4096];     // outs[bh]
    __shared__ __align__(16) float Wt[64][64];   // 64-token slicew tile
    int bh = blockIdx.x, tile = blockIdx.y, tid = threadIdx.x;
    int b = bh >> 3, h = bh & 7;
    size_t wbase = (size_t)bh * N_ * 64 + (size_t)tile * 64 * 64;

#pragma unroll
    for (int it = 0; it < 4; ++it) {
        int v = tid + (it << 8);
        *(float4*)&Ss[v << 2] = *(const float4*)&g_outs[bh * 4096 + (v << 2)];
        int rr = v >> 4, cc = (v & 15) << 2;
        *(float4*)&Wt[rr][cc] = *(const float4*)&g_slicew[wbase + (size_t)rr * 64 + cc];
    }
    __syncthreads();

    int tt0 = (tid >> 4) << 2, c0 = (tid & 15) << 2;
    float acc[4][4] = {};
    for (int g = 0; g < 64; ++g) {
        float4 sv = *(const float4*)&Ss[g * 64 + c0];
        float sa[4] = {sv.x, sv.y, sv.z, sv.w};
        float wv[4];
#pragma unroll
        for (int i = 0; i < 4; ++i) wv[i] = Wt[tt0 + i][g];
#pragma unroll
        for (int i = 0; i < 4; ++i)
#pragma unroll
            for (int j = 0; j < 4; ++j) acc[i][j] += wv[i] * sa[j];
    }
#pragma unroll
    for (int i = 0; i < 4; ++i) {
        int n = tile * 64 + tt0 + i;
        float4 v = make_float4(acc[i][0], acc[i][1], acc[i][2], acc[i][3]);
        *(float4*)&g_outx[(size_t)(b * N_ + n) * INNER_ + h * 64 + c0] = v;
    }
}

// ============================================================
extern "C" void kernel_launch(void* const* d_in, const int* in_sizes, int n_in,
                              void* d_out, int out_size)
{
    const float* x    = (const float*)d_in[0];
    const float* Wx   = (const float*)d_in[1];
    const float* bx   = (const float*)d_in[2];
    const float* W1   = (const float*)d_in[3];
    const float* b1   = (const float*)d_in[4];
    const float* W2   = (const float*)d_in[5];
    const float* b2   = (const float*)d_in[6];
    const float* bias = (const float*)d_in[7];
    const float* Ws   = (const float*)d_in[8];
    const float* bs   = (const float*)d_in[9];
    const float* Wq   = (const float*)d_in[10];
    const float* Wk   = (const float*)d_in[11];
    const float* Wv   = (const float*)d_in[12];
    const float* Wo   = (const float*)d_in[13];
    const float* bo   = (const float*)d_in[14];
    const float* u    = (const float*)d_in[15];
    float* out = (float*)d_out;

    void* outx_p = nullptr;
    cudaGetSymbolAddress(&outx_p, g_outx);

    k_zero<<<512, 256>>>();
    k_gemm<256, 512, true ><<<dim3(4, 512), 256>>>(x, Wx, bx, nullptr);
    k_route<<<dim3(32, 16), 256>>>(u, W1, b1, W2, b2, bias, Ws, bs);
    k_pool<<<dim3(32, 8), 256>>>();
    k_attn<<<32, 64>>>(Wq, Wk, Wv);
    k_scatter<<<dim3(32, 256), 256>>>();
    k_gemm<512, 256, false><<<dim3(2, 512), 256>>>((const float*)outx_p, Wo, bo, out);
}

// round 3
// speedup vs baseline: 1.9448x; 1.9448x over previous
#include <cuda_runtime.h>
#include <math.h>

#define B_     4
#define N_     16384
#define D_     256
#define H_     8
#define DH_    64
#define G_     64
#define INNER_ 512
#define BH_    32
#define M_     65536

typedef unsigned long long ull;

// ---- scratch ----
__device__ float g_xmid  [(size_t)BH_ * N_ * DH_];   // [B,H,N,DH]
__device__ float g_slicew[(size_t)BH_ * N_ * G_];    // [B,H,N,G]
__device__ float g_norm  [BH_ * G_];
__device__ float g_tok   [BH_ * G_ * DH_];
__device__ float g_outs  [BH_ * G_ * DH_];
__device__ float g_P     [(size_t)B_ * D_ * INNER_]; // [b][d][h*64+g]

__device__ __forceinline__ ull pk2(float lo, float hi) {
    ull r; asm("mov.b64 %0, {%1,%2};" : "=l"(r) : "f"(lo), "f"(hi)); return r;
}
__device__ __forceinline__ void fma2(ull& d, ull a, ull b) {
    asm("fma.rn.f32x2 %0, %1, %2, %0;" : "+l"(d) : "l"(a), "l"(b));
}
__device__ __forceinline__ float2 up2(ull v) {
    float2 r; asm("mov.b64 {%0,%1}, %2;" : "=f"(r.x), "=f"(r.y) : "l"(v)); return r;
}
__device__ __forceinline__ float gelu_f(float x) {
    return 0.5f * x * (1.0f + erff(x * 0.70710678118654752f));
}

// ============================================================
__global__ void k_zero() {
    int i = blockIdx.x * 256 + threadIdx.x;
    if (i < BH_ * G_)        g_norm[i] = 0.f;
    if (i < BH_ * G_ * DH_)  g_tok[i]  = 0.f;
}

// ============================================================
// SGEMM 128x128 tile, BK=16, 256 thr, 8x8/thread, f32x2 acc.
// MODE 1: A plain, C scattered into g_xmid [B,H,N,DH].
// MODE 2: A gathered from g_slicew (k=h*64+g), W = g_P per batch, C plain.
// ============================================================
template<int K, int NOUT, int MODE>
__global__ void __launch_bounds__(256) k_gemm(const float* __restrict__ A,
                                              const float* __restrict__ W,
                                              const float* __restrict__ bias,
                                              float* __restrict__ C)
{
    __shared__ __align__(16) float As[16][132];
    __shared__ __align__(16) float Bs[16][132];
    const int t   = threadIdx.x;
    const int gm0 = blockIdx.y << 7;
    const int gn0 = blockIdx.x << 7;
    const int m0  = (t >> 4) << 3;
    const int n0  = (t & 15) << 3;
    const int b_idx = gm0 >> 14;
    const float* Wp = (MODE == 2) ? (g_P + ((size_t)b_idx << 17)) : W;

    ull acc[8][4];
#pragma unroll
    for (int i = 0; i < 8; ++i)
#pragma unroll
        for (int j = 0; j < 4; ++j) acc[i][j] = 0ull;

    const int r0 = t >> 2;
    const int kc = (t & 3) << 2;

    for (int k0 = 0; k0 < K; k0 += 16) {
#pragma unroll
        for (int it = 0; it < 2; ++it) {
            int r = r0 + (it << 6);
            float4 av;
            if (MODE == 2) {
                int h = k0 >> 6;
                size_t aoff = ((size_t)((b_idx << 3) + h) * N_ + ((gm0 + r) & (N_ - 1))) * 64
                              + (k0 & 63) + kc;
                av = *(const float4*)(g_slicew + aoff);
            } else {
                av = *(const float4*)(A + (size_t)(gm0 + r) * K + k0 + kc);
            }
            As[kc + 0][r] = av.x; As[kc + 1][r] = av.y;
            As[kc + 2][r] = av.z; As[kc + 3][r] = av.w;
            float4 wv = *(const float4*)(Wp + (size_t)(gn0 + r) * K + k0 + kc);
            Bs[kc + 0][r] = wv.x; Bs[kc + 1][r] = wv.y;
            Bs[kc + 2][r] = wv.z; Bs[kc + 3][r] = wv.w;
        }
        __syncthreads();
#pragma unroll
        for (int kk = 0; kk < 16; ++kk) {
            float4 b0 = *(const float4*)&Bs[kk][n0];
            float4 b1 = *(const float4*)&Bs[kk][n0 + 4];
            ull bp[4] = { pk2(b0.x, b0.y), pk2(b0.z, b0.w),
                          pk2(b1.x, b1.y), pk2(b1.z, b1.w) };
            float4 a0 = *(const float4*)&As[kk][m0];
            float4 a1 = *(const float4*)&As[kk][m0 + 4];
            float am[8] = {a0.x, a0.y, a0.z, a0.w, a1.x, a1.y, a1.z, a1.w};
#pragma unroll
            for (int i = 0; i < 8; ++i) {
                ull as_ = pk2(am[i], am[i]);
#pragma unroll
                for (int j = 0; j < 4; ++j) fma2(acc[i][j], as_, bp[j]);
            }
        }
        __syncthreads();
    }

    float bv[8];
#pragma unroll
    for (int j = 0; j < 8; ++j) bv[j] = bias[gn0 + n0 + j];

#pragma unroll
    for (int i = 0; i < 8; ++i) {
        float o[8];
#pragma unroll
        for (int j = 0; j < 4; ++j) {
            float2 p = up2(acc[i][j]);
            o[2 * j]     = p.x + bv[2 * j];
            o[2 * j + 1] = p.y + bv[2 * j + 1];
        }
        int m = gm0 + m0 + i;
        float4 v0 = make_float4(o[0], o[1], o[2], o[3]);
        float4 v1 = make_float4(o[4], o[5], o[6], o[7]);
        if (MODE == 1) {
            int b = m >> 14, n = m & (N_ - 1);
            int col = gn0 + n0;
            int h = col >> 6, c0 = col & 63;
            float* dst = g_xmid + (((size_t)(b * H_ + h) * N_ + n) * DH_ + c0);
            *(float4*)dst = v0; *(float4*)(dst + 4) = v1;
        } else {
            float* dst = C + (size_t)m * NOUT + gn0 + n0;
            *(float4*)dst = v0; *(float4*)(dst + 4) = v1;
        }
    }
}

// ============================================================
// Routing, lane-per-token. Warp processes 32 tokens per iter.
// Weights broadcast from smem as packed {W1,Ws} pairs; f32x2
// dual accumulation of hidden & logit; logits kept in registers.
// Dynamic smem: wp4 32KB | xs 64KB | hb 512B | W2s 256B.
// ============================================================
__global__ void __launch_bounds__(256, 2) k_route(const float* __restrict__ u,
    const float* __restrict__ W1, const float* __restrict__ b1,
    const float* __restrict__ W2, const float* __restrict__ b2,
    const float* __restrict__ biasH, const float* __restrict__ Ws,
    const float* __restrict__ bs)
{
    extern __shared__ __align__(16) char sm_[];
    float4* wp4 = (float4*)sm_;                       // [c][32 pairs]
    float*  xs  = (float*)(sm_ + 32768);              // [warp][c][lane]
    float2* hb  = (float2*)(sm_ + 32768 + 65536);     // {b1,bs}[64]
    float*  W2s = (float*)(sm_ + 32768 + 65536 + 512);

    const int bh   = blockIdx.x;
    const int tid  = threadIdx.x;
    const int wid  = tid >> 5;
    const int lane = tid & 31;

    for (int i = tid; i < 2048; i += 256) {
        int c = i >> 5, p = i & 31;
        wp4[c * 32 + p] = make_float4(W1[(2 * p) * 64 + c],     Ws[(2 * p) * 64 + c],
                                      W1[(2 * p + 1) * 64 + c], Ws[(2 * p + 1) * 64 + c]);
    }
    if (tid < 64) { hb[tid] = make_float2(b1[tid], bs[tid]); W2s[tid] = W2[tid]; }
    __syncthreads();

    const float b2v   = b2[0];
    const float biasv = biasH[bh & 7];
    const size_t bhbase = (size_t)bh * N_ * 64;
    float* xw = xs + wid * 2048;

    for (int it = 0; it < 4; ++it) {
        const int n = blockIdx.y * 1024 + wid * 128 + it * 32 + lane;
        const size_t off = bhbase + (size_t)n * 64;

        // stage x row-per-lane -> transposed smem tile
        const float* xrow = g_xmid + off;
#pragma unroll
        for (int j = 0; j < 16; ++j) {
            float4 v = *(const float4*)(xrow + 4 * j);
            xw[(4 * j + 0) * 32 + lane] = v.x;
            xw[(4 * j + 1) * 32 + lane] = v.y;
            xw[(4 * j + 2) * 32 + lane] = v.z;
            xw[(4 * j + 3) * 32 + lane] = v.w;
        }
        __syncwarp();

        float w_[64];
        float tacc = 0.f;
#pragma unroll
        for (int gt = 0; gt < 4; ++gt) {
            ull acc[16];
#pragma unroll
            for (int j = 0; j < 16; ++j) acc[j] = *(ull*)&hb[gt * 16 + j];
#pragma unroll 8
            for (int c = 0; c < 64; ++c) {
                float xv = xw[c * 32 + lane];
                ull xp = pk2(xv, xv);
                const ulonglong2* wrow = (const ulonglong2*)(wp4 + c * 32) + gt * 8;
#pragma unroll
                for (int p = 0; p < 8; ++p) {
                    ulonglong2 wv = wrow[p];
                    fma2(acc[2 * p],     xp, wv.x);
                    fma2(acc[2 * p + 1], xp, wv.y);
                }
            }
#pragma unroll
            for (int j = 0; j < 16; ++j) {
                float2 pr = up2(acc[j]);
                tacc += gelu_f(pr.x) * W2s[gt * 16 + j];
                w_[gt * 16 + j] = pr.y;
            }
        }
        __syncwarp();

        float temp = fmaxf(gelu_f(tacc + b2v) + biasv, 0.01f);
        float itmp = 1.f / temp;

        const float* urow = u + off;
        float mx = -1e30f;
#pragma unroll
        for (int j = 0; j < 16; ++j) {
            float4 uv = *(const float4*)(urow + 4 * j);
            float ua[4] = {uv.x, uv.y, uv.z, uv.w};
#pragma unroll
            for (int q = 0; q < 4; ++q) {
                float gn = -__logf(-__logf(ua[q] + 1e-8f) + 1e-8f);
                float z = (w_[4 * j + q] + gn) * itmp;
                w_[4 * j + q] = z;
                mx = fmaxf(mx, z);
            }
        }
        float ssum = 0.f;
#pragma unroll
        for (int g = 0; g < 64; ++g) { float e = __expf(w_[g] - mx); w_[g] = e; ssum += e; }
        float inv = 1.f / ssum;

        float* srow = g_slicew + off;
#pragma unroll
        for (int j = 0; j < 16; ++j) {
            *(float4*)(srow + 4 * j) = make_float4(w_[4 * j] * inv, w_[4 * j + 1] * inv,
                                                   w_[4 * j + 2] * inv, w_[4 * j + 3] * inv);
        }
    }
}

// ============================================================
// Pooling + norm: tok[g][c] = sum_n sw[n][g]*x[n][c]; norm[g]=sum_n sw[n][g]
// ============================================================
__global__ void __launch_bounds__(256) k_pool()
{
    __shared__ __align__(16) float Xs[64][64];
    __shared__ __align__(16) float Wp[64][64];
    int bh = blockIdx.x, chunk = blockIdx.y;   // 32 chunks * 512 tokens
    int tid = threadIdx.x;
    int c0 = (tid & 15) << 2;
    int g0 = (tid >> 4) << 2;
    float acc[4][4] = {};
    float nacc[4] = {0.f, 0.f, 0.f, 0.f};
    size_t base = (size_t)bh * N_ * 64 + (size_t)chunk * 512 * 64;

    for (int t0 = 0; t0 < 512; t0 += 64) {
#pragma unroll
        for (int it = 0; it < 4; ++it) {
            int v = tid + (it << 8);
            int rr = v >> 4, cc = (v & 15) << 2;
            *(float4*)&Xs[rr][cc] = *(const float4*)&g_xmid  [base + (size_t)(t0 + rr) * 64 + cc];
            *(float4*)&Wp[rr][cc] = *(const float4*)&g_slicew[base + (size_t)(t0 + rr) * 64 + cc];
        }
        __syncthreads();
#pragma unroll
        for (int tt2 = 0; tt2 < 64; ++tt2) {
            float4 xv = *(const float4*)&Xs[tt2][c0];
            float4 wv = *(const float4*)&Wp[tt2][g0];
            float xa[4] = {xv.x, xv.y, xv.z, xv.w};
            float wa[4] = {wv.x, wv.y, wv.z, wv.w};
#pragma unroll
            for (int j = 0; j < 4; ++j) {
                nacc[j] += wa[j];
#pragma unroll
                for (int i = 0; i < 4; ++i) acc[j][i] += wa[j] * xa[i];
            }
        }
        __syncthreads();
    }
#pragma unroll
    for (int j = 0; j < 4; ++j) {
#pragma unroll
        for (int i = 0; i < 4; ++i)
            atomicAdd(&g_tok[bh * 4096 + (g0 + j) * 64 + (c0 + i)], acc[j][i]);
        if (c0 == 0) atomicAdd(&g_norm[bh * 64 + g0 + j], nacc[j]);
    }
}

// ============================================================
// Slice attention (V eliminated: out = (softmax(qk) @ T) @ Wv^T)
// ============================================================
__global__ void __launch_bounds__(64) k_attn(const float* __restrict__ Wq,
                                             const float* __restrict__ Wk,
                                             const float* __restrict__ Wv)
{
    __shared__ float T [64 * 65];
    __shared__ float Ks[64 * 64];
    int bh = blockIdx.x, tid = threadIdx.x;

    for (int i = tid; i < 4096; i += 64) {
        int g = i >> 6, c = i & 63;
        T[g * 65 + c] = g_tok[bh * 4096 + i] / (g_norm[bh * 64 + g] + 1e-5f);
    }
    __syncthreads();

    int g = tid;
    float q[64];
    for (int c = 0; c < 64; ++c) {
        float s0 = 0.f, s1 = 0.f;
        for (int k = 0; k < 64; k += 2) {
            s0 += T[g * 65 + k]     * Wq[c * 64 + k];
            s1 += T[g * 65 + k + 1] * Wq[c * 64 + k + 1];
        }
        q[c] = s0 + s1;
    }
    for (int c = 0; c < 64; ++c) {
        float s0 = 0.f, s1 = 0.f;
        for (int k = 0; k < 64; k += 2) {
            s0 += T[g * 65 + k]     * Wk[c * 64 + k];
            s1 += T[g * 65 + k + 1] * Wk[c * 64 + k + 1];
        }
        Ks[g * 64 + c] = s0 + s1;
    }
    __syncthreads();

    float sc[64];
    for (int j = 0; j < 64; ++j) {
        float s0 = 0.f, s1 = 0.f;
        for (int c = 0; c < 64; c += 2) {
            s0 += q[c]     * Ks[j * 64 + c];
            s1 += q[c + 1] * Ks[j * 64 + c + 1];
        }
        sc[j] = (s0 + s1) * 0.125f;
    }
    float mx = -1e30f;
    for (int j = 0; j < 64; ++j) mx = fmaxf(mx, sc[j]);
    float sum = 0.f;
    for (int j = 0; j < 64; ++j) { sc[j] = expf(sc[j] - mx); sum += sc[j]; }
    float inv = 1.f / sum;

    float pv[64];
    for (int c = 0; c < 64; ++c) {
        float s0 = 0.f, s1 = 0.f;
        for (int j = 0; j < 64; j += 2) {
            s0 += sc[j]     * T[j * 65 + c];
            s1 += sc[j + 1] * T[(j + 1) * 65 + c];
        }
        pv[c] = (s0 + s1) * inv;
    }
    for (int c = 0; c < 64; ++c) {
        float s0 = 0.f, s1 = 0.f;
        for (int k = 0; k < 64; k += 2) {
            s0 += pv[k]     * Wv[c * 64 + k];
            s1 += pv[k + 1] * Wv[c * 64 + k + 1];
        }
        g_outs[bh * 4096 + g * 64 + c] = s0 + s1;
    }
}

// ============================================================
// P[b][d][h*64+g] = sum_c outs[bh][g][c] * Wo[d][h*64+c]
// ============================================================
__global__ void __launch_bounds__(256) k_pmat(const float* __restrict__ Wo)
{
    __shared__ float os [64][65];
    __shared__ float wsm[64][64];
    int bh = blockIdx.x, b = bh >> 3, h = bh & 7, tid = threadIdx.x;
    for (int i = tid; i < 4096; i += 256) os[i >> 6][i & 63] = g_outs[bh * 4096 + i];
    int g = tid & 63, dl = tid >> 6;

    for (int tile = 0; tile < 4; ++tile) {
        __syncthreads();
        for (int i = tid; i < 4096; i += 256) {
            int dr = i >> 6, c = i & 63;
            wsm[dr][c] = Wo[(size_t)(tile * 64 + dr) * 512 + h * 64 + c];
        }
        __syncthreads();
#pragma unroll
        for (int ds = 0; ds < 16; ++ds) {
            int dloc = dl * 16 + ds;
            float s = 0.f;
#pragma unroll 8
            for (int c = 0; c < 64; ++c) s += wsm[dloc][c] * os[g][c];
            g_P[((size_t)b * 256 + tile * 64 + dloc) * 512 + h * 64 + g] = s;
        }
    }
}

// ============================================================
extern "C" void kernel_launch(void* const* d_in, const int* in_sizes, int n_in,
                              void* d_out, int out_size)
{
    const float* x    = (const float*)d_in[0];
    const float* Wx   = (const float*)d_in[1];
    const float* bx   = (const float*)d_in[2];
    const float* W1   = (const float*)d_in[3];
    const float* b1   = (const float*)d_in[4];
    const float* W2   = (const float*)d_in[5];
    const float* b2   = (const float*)d_in[6];
    const float* bias = (const float*)d_in[7];
    const float* Ws   = (const float*)d_in[8];
    const float* bs   = (const float*)d_in[9];
    const float* Wq   = (const float*)d_in[10];
    const float* Wk   = (const float*)d_in[11];
    const float* Wv   = (const float*)d_in[12];
    const float* Wo   = (const float*)d_in[13];
    const float* bo   = (const float*)d_in[14];
    const float* u    = (const float*)d_in[15];
    float* out = (float*)d_out;

    static int smem_set = 0;
    if (!smem_set) {
        cudaFuncSetAttribute(k_route, cudaFuncAttributeMaxDynamicSharedMemorySize, 99072);
        smem_set = 1;
    }

    k_zero<<<512, 256>>>();
    k_gemm<256, 512, 1><<<dim3(4, 512), 256>>>(x, Wx, bx, nullptr);
    k_route<<<dim3(32, 16), 256, 99072>>>(u, W1, b1, W2, b2, bias, Ws, bs);
    k_pool<<<dim3(32, 32), 256>>>();
    k_attn<<<32, 64>>>(Wq, Wk, Wv);
    k_pmat<<<32, 256>>>(Wo);
    k_gemm<512, 256, 2><<<dim3(2, 512), 256>>>(nullptr, nullptr, bo, out);
}

// round 7
// speedup vs baseline: 2.4593x; 1.2646x over previous
#include <cuda_runtime.h>
#include <cuda_bf16.h>
#include <cstdint>
#include <math.h>

#define B_     4
#define N_     16384
#define D_     256
#define H_     8
#define DH_    64
#define G_     64
#define INNER_ 512
#define BH_    32
#define M_     65536

typedef unsigned long long ull;

// ---- scratch ----
__device__ float g_xmid  [(size_t)BH_ * N_ * DH_];   // [B,H,N,DH]
__device__ float g_slicew[(size_t)BH_ * N_ * G_];    // [B,H,N,G]
__device__ float g_norm  [BH_ * G_];
__device__ float g_tok   [BH_ * G_ * DH_];
__device__ float g_outs  [BH_ * G_ * DH_];
__device__ float g_P     [(size_t)B_ * D_ * INNER_]; // [b][d][h*64+g]

__device__ __forceinline__ ull pk2(float lo, float hi) {
    ull r; asm("mov.b64 %0, {%1,%2};" : "=l"(r) : "f"(lo), "f"(hi)); return r;
}
__device__ __forceinline__ void fma2(ull& d, ull a, ull b) {
    asm("fma.rn.f32x2 %0, %1, %2, %0;" : "+l"(d) : "l"(a), "l"(b));
}
__device__ __forceinline__ float2 up2(ull v) {
    float2 r; asm("mov.b64 {%0,%1}, %2;" : "=f"(r.x), "=f"(r.y) : "l"(v)); return r;
}
__device__ __forceinline__ float gelu_f(float x) {
    return 0.5f * x * (1.0f + erff(x * 0.70710678118654752f));
}
__device__ __forceinline__ uint32_t smem_u32(const void* p) {
    uint32_t a; asm("{ .reg .u64 t; cvta.to.shared.u64 t, %1; cvt.u32.u64 %0, t; }"
                    : "=r"(a) : "l"(p));
    return a;
}

// ---- warp-level tensor ops (base sm_80+ target; NO tcgen05 on compute_103) ----
__device__ __forceinline__ void ldsm4(uint32_t& r0, uint32_t& r1, uint32_t& r2,
                                      uint32_t& r3, uint32_t addr) {
    asm volatile("ldmatrix.sync.aligned.m8n8.x4.shared.b16 {%0,%1,%2,%3}, [%4];"
                 : "=r"(r0), "=r"(r1), "=r"(r2), "=r"(r3) : "r"(addr));
}
__device__ __forceinline__ void mma16816(float* c, const uint32_t* a,
                                         uint32_t b0, uint32_t b1) {
    asm volatile("mma.sync.aligned.m16n8k16.row.col.f32.bf16.bf16.f32 "
                 "{%0,%1,%2,%3}, {%4,%5,%6,%7}, {%8,%9}, {%0,%1,%2,%3};"
                 : "+f"(c[0]), "+f"(c[1]), "+f"(c[2]), "+f"(c[3])
                 : "r"(a[0]), "r"(a[1]), "r"(a[2]), "r"(a[3]), "r"(b0), "r"(b1));
}

// smem layout for mma gemm (dynamic, 64KB): Ah|Al|Bh|Bl, each 128rows x 128B, SW128
#define SM_AH 0
#define SM_AL 16384
#define SM_BH 32768
#define SM_BL 49152
#define SM_TC_TOTAL 65536

__device__ __forceinline__ void cvt_split4(float4 v, uint2& hi, uint2& lo) {
    __nv_bfloat16 hx = __float2bfloat16(v.x), hy = __float2bfloat16(v.y);
    __nv_bfloat16 hz = __float2bfloat16(v.z), hw = __float2bfloat16(v.w);
    __nv_bfloat16 lx = __float2bfloat16(v.x - __bfloat162float(hx));
    __nv_bfloat16 ly = __float2bfloat16(v.y - __bfloat162float(hy));
    __nv_bfloat16 lz = __float2bfloat16(v.z - __bfloat162float(hz));
    __nv_bfloat16 lw = __float2bfloat16(v.w - __bfloat162float(hw));
    hi.x = (uint32_t)__bfloat16_as_ushort(hx) | ((uint32_t)__bfloat16_as_ushort(hy) << 16);
    hi.y = (uint32_t)__bfloat16_as_ushort(hz) | ((uint32_t)__bfloat16_as_ushort(hw) << 16);
    lo.x = (uint32_t)__bfloat16_as_ushort(lx) | ((uint32_t)__bfloat16_as_ushort(ly) << 16);
    lo.y = (uint32_t)__bfloat16_as_ushort(lz) | ((uint32_t)__bfloat16_as_ushort(lw) << 16);
}

// ============================================================
__global__ void k_zero() {
    int i = blockIdx.x * 256 + threadIdx.x;
    if (i < BH_ * G_)        g_norm[i] = 0.f;
    if (i < BH_ * G_ * DH_)  g_tok[i]  = 0.f;
}

// ============================================================
// Split-bf16 HMMA GEMM. CTA 128x128, K chunks of 64, 8 warps 4x2.
// D = Ah*Bh + Ah*Bl + Al*Bh, fp32 accum in registers.
// MODE 1: A plain fp32 [M][K], C scattered into g_xmid [B,H,N,DH].
// MODE 2: A gathered from g_slicew (k=h*64+g), W=g_P[b], C plain.
// ============================================================
template<int KTOT, int MODE>
__global__ void __launch_bounds__(256)
k_gemm_tc(const float* __restrict__ A, const float* __restrict__ W,
          const float* __restrict__ bias, float* __restrict__ C)
{
    extern __shared__ __align__(1024) char sm_[];
    const uint32_t smb = smem_u32(sm_);
    const int tid  = threadIdx.x;
    const int wid  = tid >> 5;
    const int lane = tid & 31;
    const int gm0  = blockIdx.y << 7;
    const int gn0  = blockIdx.x << 7;
    const int b_idx = gm0 >> 14;
    const int wm = (wid >> 1) << 5;     // warp M offset (0,32,64,96)
    const int wn = (wid & 1)  << 6;     // warp N offset (0,64)

    float acc[2][8][4];
#pragma unroll
    for (int i = 0; i < 2; ++i)
#pragma unroll
        for (int j = 0; j < 8; ++j)
#pragma unroll
            for (int q = 0; q < 4; ++q) acc[i][j][q] = 0.f;

    // precomputed ldmatrix lane offsets (byte, pre-swizzle)
    const int a_row = (lane & 15);
    const int a_chk = (lane >> 4) << 4;
    const int b_row = (lane & 7) + (((lane >> 4) & 1) << 3);   // within 16-row pair
    const int b_chk = ((lane >> 3) & 1) << 4;

    const int NCH = KTOT / 64;
    for (int ch = 0; ch < NCH; ++ch) {
        const int k0 = ch << 6;
        // ---- load + convert fp32 -> bf16 hi/lo into swizzled smem ----
#pragma unroll
        for (int i = 0; i < 8; ++i) {
            int idx = tid + (i << 8);          // 0..2047
            int row = idx >> 4, quad = idx & 15;
            float4 av, wv;
            if (MODE == 2) {
                int m = gm0 + row, n = m & (N_ - 1);
                int h = k0 >> 6;
                av = *(const float4*)(g_slicew +
                        ((size_t)((b_idx << 3) + h) * N_ + n) * 64 + (quad << 2));
                wv = *(const float4*)(g_P + ((size_t)b_idx << 17)
                        + (size_t)(gn0 + row) * 512 + k0 + (quad << 2));
            } else {
                av = *(const float4*)(A + (size_t)(gm0 + row) * KTOT + k0 + (quad << 2));
                wv = *(const float4*)(W + (size_t)(gn0 + row) * KTOT + k0 + (quad << 2));
            }
            uint32_t off = (row << 7) + (quad << 3);
            uint32_t sw  = off ^ ((off >> 3) & 0x70);
            uint2 hi, lo;
            cvt_split4(av, hi, lo);
            *(uint2*)(sm_ + SM_AH + sw) = hi;
            *(uint2*)(sm_ + SM_AL + sw) = lo;
            cvt_split4(wv, hi, lo);
            *(uint2*)(sm_ + SM_BH + sw) = hi;
            *(uint2*)(sm_ + SM_BL + sw) = lo;
        }
        __syncthreads();

        // ---- compute: 4 k16-steps, 3 products ----
#pragma unroll
        for (int ks = 0; ks < 4; ++ks) {
            const int kb = ks << 5;            // 16 bf16 = 32 bytes
            uint32_t ah[2][4], al[2][4];
#pragma unroll
            for (int mt = 0; mt < 2; ++mt) {
                uint32_t bo = ((wm + (mt << 4) + a_row) << 7) + kb + a_chk;
                uint32_t sw = bo ^ ((bo >> 3) & 0x70);
                ldsm4(ah[mt][0], ah[mt][1], ah[mt][2], ah[mt][3], smb + SM_AH + sw);
                ldsm4(al[mt][0], al[mt][1], al[mt][2], al[mt][3], smb + SM_AL + sw);
            }
#pragma unroll
            for (int p2 = 0; p2 < 4; ++p2) {
                uint32_t bo = ((wn + (p2 << 4) + b_row) << 7) + kb + b_chk;
                uint32_t sw = bo ^ ((bo >> 3) & 0x70);
                uint32_t bh0, bh1, bh2, bh3, bl0, bl1, bl2, bl3;
                ldsm4(bh0, bh1, bh2, bh3, smb + SM_BH + sw);
                ldsm4(bl0, bl1, bl2, bl3, smb + SM_BL + sw);
#pragma unroll
                for (int mt = 0; mt < 2; ++mt) {
                    mma16816(acc[mt][2 * p2],     ah[mt], bh0, bh1);
                    mma16816(acc[mt][2 * p2 + 1], ah[mt], bh2, bh3);
                    mma16816(acc[mt][2 * p2],     ah[mt], bl0, bl1);
                    mma16816(acc[mt][2 * p2 + 1], ah[mt], bl2, bl3);
                    mma16816(acc[mt][2 * p2],     al[mt], bh0, bh1);
                    mma16816(acc[mt][2 * p2 + 1], al[mt], bh2, bh3);
                }
            }
        }
        __syncthreads();
    }

    // ---- epilogue ----
    const int grp = lane >> 2, qid = (lane & 3) << 1;
#pragma unroll
    for (int mt = 0; mt < 2; ++mt) {
#pragma unroll
        for (int nt = 0; nt < 8; ++nt) {
            int col = gn0 + wn + (nt << 3) + qid;
            float bv0 = bias[col], bv1 = bias[col + 1];
            int r0 = gm0 + wm + (mt << 4) + grp;
            float2 v0 = make_float2(acc[mt][nt][0] + bv0, acc[mt][nt][1] + bv1);
            float2 v1 = make_float2(acc[mt][nt][2] + bv0, acc[mt][nt][3] + bv1);
            if (MODE == 1) {
                int bb = r0 >> 14, n = r0 & (N_ - 1);
                int h = col >> 6, c = col & 63;
                float* d0 = g_xmid + (((size_t)((bb << 3) + h) * N_ + n) << 6) + c;
                *(float2*)d0 = v0;
                *(float2*)(d0 + (8 << 6)) = v1;      // row+8, same b/h
            } else {
                float* d0 = C + (size_t)r0 * 256 + col;
                *(float2*)d0 = v0;
                *(float2*)(d0 + (size_t)8 * 256) = v1;
            }
        }
    }
}

// ============================================================
// Routing, lane-per-token (unchanged from passing R3 version).
// ============================================================
__global__ void __launch_bounds__(256, 2) k_route(const float* __restrict__ u,
    const float* __restrict__ W1, const float* __restrict__ b1,
    const float* __restrict__ W2, const float* __restrict__ b2,
    const float* __restrict__ biasH, const float* __restrict__ Ws,
    const float* __restrict__ bs)
{
    extern __shared__ __align__(1024) char sm_[];
    float4* wp4 = (float4*)sm_;
    float*  xs  = (float*)(sm_ + 32768);
    float2* hb  = (float2*)(sm_ + 32768 + 65536);
    float*  W2s = (float*)(sm_ + 32768 + 65536 + 512);

    const int bh   = blockIdx.x;
    const int tid  = threadIdx.x;
    const int wid  = tid >> 5;
    const int lane = tid & 31;

    for (int i = tid; i < 2048; i += 256) {
        int c = i >> 5, p = i & 31;
        wp4[c * 32 + p] = make_float4(W1[(2 * p) * 64 + c],     Ws[(2 * p) * 64 + c],
                                      W1[(2 * p + 1) * 64 + c], Ws[(2 * p + 1) * 64 + c]);
    }
    if (tid < 64) { hb[tid] = make_float2(b1[tid], bs[tid]); W2s[tid] = W2[tid]; }
    __syncthreads();

    const float b2v   = b2[0];
    const float biasv = biasH[bh & 7];
    const size_t bhbase = (size_t)bh * N_ * 64;
    float* xw = xs + wid * 2048;

    for (int it = 0; it < 4; ++it) {
        const int n = blockIdx.y * 1024 + wid * 128 + it * 32 + lane;
        const size_t off = bhbase + (size_t)n * 64;

        const float* xrow = g_xmid + off;
#pragma unroll
        for (int j = 0; j < 16; ++j) {
            float4 v = *(const float4*)(xrow + 4 * j);
            xw[(4 * j + 0) * 32 + lane] = v.x;
            xw[(4 * j + 1) * 32 + lane] = v.y;
            xw[(4 * j + 2) * 32 + lane] = v.z;
            xw[(4 * j + 3) * 32 + lane] = v.w;
        }
        __syncwarp();

        float w_[64];
        float tacc = 0.f;
#pragma unroll
        for (int gt = 0; gt < 4; ++gt) {
            ull acc[16];
#pragma unroll
            for (int j = 0; j < 16; ++j) acc[j] = *(ull*)&hb[gt * 16 + j];
#pragma unroll 8
            for (int c = 0; c < 64; ++c) {
                float xv = xw[c * 32 + lane];
                ull xp = pk2(xv, xv);
                const ulonglong2* wrow = (const ulonglong2*)(wp4 + c * 32) + gt * 8;
#pragma unroll
                for (int p = 0; p < 8; ++p) {
                    ulonglong2 wv = wrow[p];
                    fma2(acc[2 * p],     xp, wv.x);
                    fma2(acc[2 * p + 1], xp, wv.y);
                }
            }
#pragma unroll
            for (int j = 0; j < 16; ++j) {
                float2 pr = up2(acc[j]);
                tacc += gelu_f(pr.x) * W2s[gt * 16 + j];
                w_[gt * 16 + j] = pr.y;
            }
        }
        __syncwarp();

        float temp = fmaxf(gelu_f(tacc + b2v) + biasv, 0.01f);
        float itmp = 1.f / temp;

        const float* urow = u + off;
        float mx = -1e30f;
#pragma unroll
        for (int j = 0; j < 16; ++j) {
            float4 uv = *(const float4*)(urow + 4 * j);
            float ua[4] = {uv.x, uv.y, uv.z, uv.w};
#pragma unroll
            for (int q = 0; q < 4; ++q) {
                float gn = -__logf(-__logf(ua[q] + 1e-8f) + 1e-8f);
                float z = (w_[4 * j + q] + gn) * itmp;
                w_[4 * j + q] = z;
                mx = fmaxf(mx, z);
            }
        }
        float ssum = 0.f;
#pragma unroll
        for (int g = 0; g < 64; ++g) { float e = __expf(w_[g] - mx); w_[g] = e; ssum += e; }
        float inv = 1.f / ssum;

        float* srow = g_slicew + off;
#pragma unroll
        for (int j = 0; j < 16; ++j) {
            *(float4*)(srow + 4 * j) = make_float4(w_[4 * j] * inv, w_[4 * j + 1] * inv,
                                                   w_[4 * j + 2] * inv, w_[4 * j + 3] * inv);
        }
    }
}

// ============================================================
// Pooling + norm (unchanged).
// ============================================================
__global__ void __launch_bounds__(256) k_pool()
{
    __shared__ __align__(16) float Xs[64][64];
    __shared__ __align__(16) float Wp[64][64];
    int bh = blockIdx.x, chunk = blockIdx.y;
    int tid = threadIdx.x;
    int c0 = (tid & 15) << 2;
    int g0 = (tid >> 4) << 2;
    float acc[4][4] = {};
    float nacc[4] = {0.f, 0.f, 0.f, 0.f};
    size_t base = (size_t)bh * N_ * 64 + (size_t)chunk * 512 * 64;

    for (int t0 = 0; t0 < 512; t0 += 64) {
#pragma unroll
        for (int it = 0; it < 4; ++it) {
            int v = tid + (it << 8);
            int rr = v >> 4, cc = (v & 15) << 2;
            *(float4*)&Xs[rr][cc] = *(const float4*)&g_xmid  [base + (size_t)(t0 + rr) * 64 + cc];
            *(float4*)&Wp[rr][cc] = *(const float4*)&g_slicew[base + (size_t)(t0 + rr) * 64 + cc];
        }
        __syncthreads();
#pragma unroll
        for (int tt2 = 0; tt2 < 64; ++tt2) {
            float4 xv = *(const float4*)&Xs[tt2][c0];
            float4 wv = *(const float4*)&Wp[tt2][g0];
            float xa[4] = {xv.x, xv.y, xv.z, xv.w};
            float wa[4] = {wv.x, wv.y, wv.z, wv.w};
#pragma unroll
            for (int j = 0; j < 4; ++j) {
                nacc[j] += wa[j];
#pragma unroll
                for (int i = 0; i < 4; ++i) acc[j][i] += wa[j] * xa[i];
            }
        }
        __syncthreads();
    }
#pragma unroll
    for (int j = 0; j < 4; ++j) {
#pragma unroll
        for (int i = 0; i < 4; ++i)
            atomicAdd(&g_tok[bh * 4096 + (g0 + j) * 64 + (c0 + i)], acc[j][i]);
        if (c0 == 0) atomicAdd(&g_norm[bh * 64 + g0 + j], nacc[j]);
    }
}

// ============================================================
// Slice attention (unchanged).
// ============================================================
__global__ void __launch_bounds__(64) k_attn(const float* __restrict__ Wq,
                                             const float* __restrict__ Wk,
                                             const float* __restrict__ Wv)
{
    __shared__ float T [64 * 65];
    __shared__ float Ks[64 * 64];
    int bh = blockIdx.x, tid = threadIdx.x;

    for (int i = tid; i < 4096; i += 64) {
        int g = i >> 6, c = i & 63;
        T[g * 65 + c] = g_tok[bh * 4096 + i] / (g_norm[bh * 64 + g] + 1e-5f);
    }
    __syncthreads();

    int g = tid;
    float q[64];
    for (int c = 0; c < 64; ++c) {
        float s0 = 0.f, s1 = 0.f;
        for (int k = 0; k < 64; k += 2) {
            s0 += T[g * 65 + k]     * Wq[c * 64 + k];
            s1 += T[g * 65 + k + 1] * Wq[c * 64 + k + 1];
        }
        q[c] = s0 + s1;
    }
    for (int c = 0; c < 64; ++c) {
        float s0 = 0.f, s1 = 0.f;
        for (int k = 0; k < 64; k += 2) {
            s0 += T[g * 65 + k]     * Wk[c * 64 + k];
            s1 += T[g * 65 + k + 1] * Wk[c * 64 + k + 1];
        }
        Ks[g * 64 + c] = s0 + s1;
    }
    __syncthreads();

    float sc[64];
    for (int j = 0; j < 64; ++j) {
        float s0 = 0.f, s1 = 0.f;
        for (int c = 0; c < 64; c += 2) {
            s0 += q[c]     * Ks[j * 64 + c];
            s1 += q[c + 1] * Ks[j * 64 + c + 1];
        }
        sc[j] = (s0 + s1) * 0.125f;
    }
    float mx = -1e30f;
    for (int j = 0; j < 64; ++j) mx = fmaxf(mx, sc[j]);
    float sum = 0.f;
    for (int j = 0; j < 64; ++j) { sc[j] = expf(sc[j] - mx); sum += sc[j]; }
    float inv = 1.f / sum;

    float pv[64];
    for (int c = 0; c < 64; ++c) {
        float s0 = 0.f, s1 = 0.f;
        for (int j = 0; j < 64; j += 2) {
            s0 += sc[j]     * T[j * 65 + c];
            s1 += sc[j + 1] * T[(j + 1) * 65 + c];
        }
        pv[c] = (s0 + s1) * inv;
    }
    for (int c = 0; c < 64; ++c) {
        float s0 = 0.f, s1 = 0.f;
        for (int k = 0; k < 64; k += 2) {
            s0 += pv[k]     * Wv[c * 64 + k];
            s1 += pv[k + 1] * Wv[c * 64 + k + 1];
        }
        g_outs[bh * 4096 + g * 64 + c] = s0 + s1;
    }
}

// ============================================================
// P[b][d][h*64+g] = sum_c outs[bh][g][c] * Wo[d][h*64+c]  (unchanged)
// ============================================================
__global__ void __launch_bounds__(256) k_pmat(const float* __restrict__ Wo)
{
    __shared__ float os [64][65];
    __shared__ float wsm[64][64];
    int bh = blockIdx.x, b = bh >> 3, h = bh & 7, tid = threadIdx.x;
    for (int i = tid; i < 4096; i += 256) os[i >> 6][i & 63] = g_outs[bh * 4096 + i];
    int g = tid & 63, dl = tid >> 6;

    for (int tile = 0; tile < 4; ++tile) {
        __syncthreads();
        for (int i = tid; i < 4096; i += 256) {
            int dr = i >> 6, c = i & 63;
            wsm[dr][c] = Wo[(size_t)(tile * 64 + dr) * 512 + h * 64 + c];
        }
        __syncthreads();
#pragma unroll
        for (int ds = 0; ds < 16; ++ds) {
            int dloc = dl * 16 + ds;
            float s = 0.f;
#pragma unroll 8
            for (int c = 0; c < 64; ++c) s += wsm[dloc][c] * os[g][c];
            g_P[((size_t)b * 256 + tile * 64 + dloc) * 512 + h * 64 + g] = s;
        }
    }
}

// ============================================================
extern "C" void kernel_launch(void* const* d_in, const int* in_sizes, int n_in,
                              void* d_out, int out_size)
{
    const float* x    = (const float*)d_in[0];
    const float* Wx   = (const float*)d_in[1];
    const float* bx   = (const float*)d_in[2];
    const float* W1   = (const float*)d_in[3];
    const float* b1   = (const float*)d_in[4];
    const float* W2   = (const float*)d_in[5];
    const float* b2   = (const float*)d_in[6];
    const float* bias = (const float*)d_in[7];
    const float* Ws   = (const float*)d_in[8];
    const float* bs   = (const float*)d_in[9];
    const float* Wq   = (const float*)d_in[10];
    const float* Wk   = (const float*)d_in[11];
    const float* Wv   = (const float*)d_in[12];
    const float* Wo   = (const float*)d_in[13];
    const float* bo   = (const float*)d_in[14];
    const float* u    = (const float*)d_in[15];
    float* out = (float*)d_out;

    static int smem_set = 0;
    if (!smem_set) {
        cudaFuncSetAttribute(k_route, cudaFuncAttributeMaxDynamicSharedMemorySize, 99072);
        cudaFuncSetAttribute(k_gemm_tc<256, 1>, cudaFuncAttributeMaxDynamicSharedMemorySize, SM_TC_TOTAL);
        cudaFuncSetAttribute(k_gemm_tc<512, 2>, cudaFuncAttributeMaxDynamicSharedMemorySize, SM_TC_TOTAL);
        smem_set = 1;
    }

    k_zero<<<512, 256>>>();
    k_gemm_tc<256, 1><<<dim3(4, 512), 256, SM_TC_TOTAL>>>(x, Wx, bx, nullptr);
    k_route<<<dim3(32, 16), 256, 99072>>>(u, W1, b1, W2, b2, bias, Ws, bs);
    k_pool<<<dim3(32, 32), 256>>>();
    k_attn<<<32, 64>>>(Wq, Wk, Wv);
    k_pmat<<<32, 256>>>(Wo);
    k_gemm_tc<512, 2><<<dim3(2, 512), 256, SM_TC_TOTAL>>>(nullptr, nullptr, bo, out);
}

// round 10
// speedup vs baseline: 2.4879x; 1.0116x over previous
#include <cuda_runtime.h>
#include <cuda_bf16.h>
#include <cstdint>
#include <math.h>

#define B_     4
#define N_     16384
#define D_     256
#define H_     8
#define DH_    64
#define G_     64
#define INNER_ 512
#define BH_    32
#define M_     65536

typedef unsigned long long ull;

// ---- scratch ----
__device__ float g_xmid  [(size_t)BH_ * N_ * DH_];   // [B,H,N,DH]
__device__ float g_slicew[(size_t)BH_ * N_ * G_];    // [B,H,N,G] fp32 (pool)
__device__ float g_norm  [BH_ * G_];
__device__ float g_tok   [BH_ * G_ * DH_];
__device__ float g_outs  [BH_ * G_ * DH_];
// bf16 split operands for HMMA GEMMs
__device__ __nv_bfloat16 g_xh [(size_t)M_ * D_],        g_xl [(size_t)M_ * D_];
__device__ __nv_bfloat16 g_wxh[INNER_ * D_],            g_wxl[INNER_ * D_];
__device__ __nv_bfloat16 g_swh[(size_t)BH_ * N_ * G_],  g_swl[(size_t)BH_ * N_ * G_];
__device__ __nv_bfloat16 g_ph [B_ * D_ * INNER_],       g_pl [B_ * D_ * INNER_];

__device__ __forceinline__ ull pk2(float lo, float hi) {
    ull r; asm("mov.b64 %0, {%1,%2};" : "=l"(r) : "f"(lo), "f"(hi)); return r;
}
__device__ __forceinline__ void fma2(ull& d, ull a, ull b) {
    asm("fma.rn.f32x2 %0, %1, %2, %0;" : "+l"(d) : "l"(a), "l"(b));
}
__device__ __forceinline__ float2 up2(ull v) {
    float2 r; asm("mov.b64 {%0,%1}, %2;" : "=f"(r.x), "=f"(r.y) : "l"(v)); return r;
}
__device__ __forceinline__ float gelu_f(float x) {
    return 0.5f * x * (1.0f + erff(x * 0.70710678118654752f));
}
__device__ __forceinline__ uint32_t smem_u32(const void* p) {
    uint32_t a; asm("{ .reg .u64 t; cvta.to.shared.u64 t, %1; cvt.u32.u64 %0, t; }"
                    : "=r"(a) : "l"(p));
    return a;
}

// ---- warp-level tensor ops (base target; NO tcgen05 on compute_103) ----
__device__ __forceinline__ void ldsm4(uint32_t& r0, uint32_t& r1, uint32_t& r2,
                                      uint32_t& r3, uint32_t addr) {
    asm volatile("ldmatrix.sync.aligned.m8n8.x4.shared.b16 {%0,%1,%2,%3}, [%4];"
                 : "=r"(r0), "=r"(r1), "=r"(r2), "=r"(r3) : "r"(addr));
}
__device__ __forceinline__ void mma16816(float* c, const uint32_t* a,
                                         uint32_t b0, uint32_t b1) {
    asm volatile("mma.sync.aligned.m16n8k16.row.col.f32.bf16.bf16.f32 "
                 "{%0,%1,%2,%3}, {%4,%5,%6,%7}, {%8,%9}, {%0,%1,%2,%3};"
                 : "+f"(c[0]), "+f"(c[1]), "+f"(c[2]), "+f"(c[3])
                 : "r"(a[0]), "r"(a[1]), "r"(a[2]), "r"(a[3]), "r"(b0), "r"(b1));
}
__device__ __forceinline__ void cpa16(uint32_t dst, const void* src) {
    asm volatile("cp.async.cg.shared.global [%0], [%1], 16;" :: "r"(dst), "l"(src));
}
#define CP_COMMIT() asm volatile("cp.async.commit_group;" ::: "memory")
#define CP_WAIT(n)  asm volatile("cp.async.wait_group %0;" :: "n"(n) : "memory")

// per-stage smem: Ah|Al|Bh|Bl, each 128 rows x 128B (SW128). 2 stages.
#define SM_STAGE   65536
#define SM_TC_TOTAL 131072

__device__ __forceinline__ void cvt_split4(float4 v, uint2& hi, uint2& lo) {
    __nv_bfloat16 hx = __float2bfloat16(v.x), hy = __float2bfloat16(v.y);
    __nv_bfloat16 hz = __float2bfloat16(v.z), hw = __float2bfloat16(v.w);
    __nv_bfloat16 lx = __float2bfloat16(v.x - __bfloat162float(hx));
    __nv_bfloat16 ly = __float2bfloat16(v.y - __bfloat162float(hy));
    __nv_bfloat16 lz = __float2bfloat16(v.z - __bfloat162float(hz));
    __nv_bfloat16 lw = __float2bfloat16(v.w - __bfloat162float(hw));
    hi.x = (uint32_t)__bfloat16_as_ushort(hx) | ((uint32_t)__bfloat16_as_ushort(hy) << 16);
    hi.y = (uint32_t)__bfloat16_as_ushort(hz) | ((uint32_t)__bfloat16_as_ushort(hw) << 16);
    lo.x = (uint32_t)__bfloat16_as_ushort(lx) | ((uint32_t)__bfloat16_as_ushort(ly) << 16);
    lo.y = (uint32_t)__bfloat16_as_ushort(lz) | ((uint32_t)__bfloat16_as_ushort(lw) << 16);
}

// ============================================================
__global__ void k_zero() {
    int i = blockIdx.x * 256 + threadIdx.x;
    if (i < BH_ * G_)        g_norm[i] = 0.f;
    if (i < BH_ * G_ * DH_)  g_tok[i]  = 0.f;
}

// ============================================================
// fp32 -> split-bf16 pre-conversion (8 elements/thread)
// ============================================================
__global__ void __launch_bounds__(256) k_cvt(const float* __restrict__ src,
                                             __nv_bfloat16* __restrict__ dh,
                                             __nv_bfloat16* __restrict__ dl, int n8)
{
    int i = blockIdx.x * 256 + threadIdx.x;
    if (i >= n8) return;
    const float4* s = (const float4*)src + 2 * (size_t)i;
    float4 v0 = s[0], v1 = s[1];
    uint2 h0, l0, h1, l1;
    cvt_split4(v0, h0, l0); cvt_split4(v1, h1, l1);
    ((uint4*)dh)[i] = make_uint4(h0.x, h0.y, h1.x, h1.y);
    ((uint4*)dl)[i] = make_uint4(l0.x, l0.y, l1.x, l1.y);
}

// ============================================================
// Split-bf16 HMMA GEMM, pre-converted operands, cp.async 2-stage.
// CTA 128x128, K chunks of 64, 8 warps 4x2.
// MODE 1: A=[M][K] (g_xh/l), B=W rows (g_wxh/l), C scattered to g_xmid.
// MODE 2: A gathered from g_swh/l (k=h*64+g), B=g_ph/l[b], C plain.
// ============================================================
template<int KTOT, int MODE>
__global__ void __launch_bounds__(256)
k_gemm_tc(const __nv_bfloat16* __restrict__ Ah, const __nv_bfloat16* __restrict__ Al,
          const __nv_bfloat16* __restrict__ Bh, const __nv_bfloat16* __restrict__ Bl,
          const float* __restrict__ bias, float* __restrict__ C)
{
    extern __shared__ __align__(1024) char sm_[];
    const uint32_t smb = smem_u32(sm_);
    const int tid  = threadIdx.x;
    const int wid  = tid >> 5;
    const int lane = tid & 31;
    const int gm0  = blockIdx.y << 7;
    const int gn0  = blockIdx.x << 7;
    const int b_idx = gm0 >> 14;
    const int wm = (wid >> 1) << 5;
    const int wn = (wid & 1)  << 6;

    float acc[2][8][4];
#pragma unroll
    for (int i = 0; i < 2; ++i)
#pragma unroll
        for (int j = 0; j < 8; ++j)
#pragma unroll
            for (int q = 0; q < 4; ++q) acc[i][j][q] = 0.f;

    const int a_row = (lane & 15);
    const int a_chk = (lane >> 4) << 4;
    const int b_row = (lane & 7) + (((lane >> 4) & 1) << 3);
    const int b_chk = ((lane >> 3) & 1) << 4;
    const int NCH = KTOT / 64;

    // prefetch one chunk's 4 buffers into a stage
    auto prefetch = [&](int ch, int stage) {
        const int k0 = ch << 6;
        const uint32_t sb = smb + stage * SM_STAGE;
#pragma unroll
        for (int i = 0; i < 4; ++i) {           // 0=Ah 1=Al 2=Bh 3=Bl
#pragma unroll
            for (int t = 0; t < 4; ++t) {
                int j = tid + (t << 8);         // 0..1023
                int row = j >> 3, cc = j & 7;
                uint32_t off = (row << 7) + (cc << 4);
                uint32_t sw  = off ^ ((off >> 3) & 0x70);
                const __nv_bfloat16* src;
                if (i < 2) {
                    const __nv_bfloat16* base = (i == 0) ? Ah : Al;
                    if (MODE == 2) {
                        int m = gm0 + row, n = m & (N_ - 1);
                        int h = k0 >> 6;
                        src = base + ((size_t)((b_idx << 3) + h) * N_ + n) * 64 + (cc << 3);
                    } else {
                        src = base + (size_t)(gm0 + row) * KTOT + k0 + (cc << 3);
                    }
                } else {
                    const __nv_bfloat16* base = (i == 2) ? Bh : Bl;
                    if (MODE == 2)
                        src = base + ((size_t)b_idx * 256 + gn0 + row) * 512 + k0 + (cc << 3);
                    else
                        src = base + (size_t)(gn0 + row) * KTOT + k0 + (cc << 3);
                }
                cpa16(sb + (i << 14) + sw, src);
            }
        }
    };

    prefetch(0, 0); CP_COMMIT();
    int stage = 0;
    for (int ch = 0; ch < NCH; ++ch) {
        if (ch + 1 < NCH) { prefetch(ch + 1, stage ^ 1); CP_COMMIT(); CP_WAIT(1); }
        else              { CP_WAIT(0); }
        __syncthreads();

        const uint32_t sb = smb + stage * SM_STAGE;
#pragma unroll
        for (int ks = 0; ks < 4; ++ks) {
            const int kb = ks << 5;
            uint32_t ah[2][4], al[2][4];
#pragma unroll
            for (int mt = 0; mt < 2; ++mt) {
                uint32_t bo = ((wm + (mt << 4) + a_row) << 7) + kb + a_chk;
                uint32_t sw = bo ^ ((bo >> 3) & 0x70);
                ldsm4(ah[mt][0], ah[mt][1], ah[mt][2], ah[mt][3], sb + sw);
                ldsm4(al[mt][0], al[mt][1], al[mt][2], al[mt][3], sb + 16384 + sw);
            }
#pragma unroll
            for (int p2 = 0; p2 < 4; ++p2) {
                uint32_t bo = ((wn + (p2 << 4) + b_row) << 7) + kb + b_chk;
                uint32_t sw = bo ^ ((bo >> 3) & 0x70);
                uint32_t bh0, bh1, bh2, bh3, bl0, bl1, bl2, bl3;
                ldsm4(bh0, bh1, bh2, bh3, sb + 32768 + sw);
                ldsm4(bl0, bl1, bl2, bl3, sb + 49152 + sw);
#pragma unroll
                for (int mt = 0; mt < 2; ++mt) {
                    mma16816(acc[mt][2 * p2],     ah[mt], bh0, bh1);
                    mma16816(acc[mt][2 * p2 + 1], ah[mt], bh2, bh3);
                    mma16816(acc[mt][2 * p2],     ah[mt], bl0, bl1);
                    mma16816(acc[mt][2 * p2 + 1], ah[mt], bl2, bl3);
                    mma16816(acc[mt][2 * p2],     al[mt], bh0, bh1);
                    mma16816(acc[mt][2 * p2 + 1], al[mt], bh2, bh3);
                }
            }
        }
        __syncthreads();
        stage ^= 1;
    }

    // ---- epilogue ----
    const int grp = lane >> 2, qid = (lane & 3) << 1;
#pragma unroll
    for (int mt = 0; mt < 2; ++mt) {
#pragma unroll
        for (int nt = 0; nt < 8; ++nt) {
            int col = gn0 + wn + (nt << 3) + qid;
            float bv0 = bias[col], bv1 = bias[col + 1];
            int r0 = gm0 + wm + (mt << 4) + grp;
            float2 v0 = make_float2(acc[mt][nt][0] + bv0, acc[mt][nt][1] + bv1);
            float2 v1 = make_float2(acc[mt][nt][2] + bv0, acc[mt][nt][3] + bv1);
            if (MODE == 1) {
                int bb = r0 >> 14, n = r0 & (N_ - 1);
                int h = col >> 6, c = col & 63;
                float* d0 = g_xmid + (((size_t)((bb << 3) + h) * N_ + n) << 6) + c;
                *(float2*)d0 = v0;
                *(float2*)(d0 + (8 << 6)) = v1;
            } else {
                float* d0 = C + (size_t)r0 * 256 + col;
                *(float2*)d0 = v0;
                *(float2*)(d0 + (size_t)8 * 256) = v1;
            }
        }
    }
}

// ============================================================
// Routing, lane-per-token; also emits split-bf16 slicew.
// ============================================================
__global__ void __launch_bounds__(256, 2) k_route(const float* __restrict__ u,
    const float* __restrict__ W1, const float* __restrict__ b1,
    const float* __restrict__ W2, const float* __restrict__ b2,
    const float* __restrict__ biasH, const float* __restrict__ Ws,
    const float* __restrict__ bs)
{
    extern __shared__ __align__(1024) char sm_[];
    float4* wp4 = (float4*)sm_;
    float*  xs  = (float*)(sm_ + 32768);
    float2* hb  = (float2*)(sm_ + 32768 + 65536);
    float*  W2s = (float*)(sm_ + 32768 + 65536 + 512);

    const int bh   = blockIdx.x;
    const int tid  = threadIdx.x;
    const int wid  = tid >> 5;
    const int lane = tid & 31;

    for (int i = tid; i < 2048; i += 256) {
        int c = i >> 5, p = i & 31;
        wp4[c * 32 + p] = make_float4(W1[(2 * p) * 64 + c],     Ws[(2 * p) * 64 + c],
                                      W1[(2 * p + 1) * 64 + c], Ws[(2 * p + 1) * 64 + c]);
    }
    if (tid < 64) { hb[tid] = make_float2(b1[tid], bs[tid]); W2s[tid] = W2[tid]; }
    __syncthreads();

    const float b2v   = b2[0];
    const float biasv = biasH[bh & 7];
    const size_t bhbase = (size_t)bh * N_ * 64;
    float* xw = xs + wid * 2048;

    for (int it = 0; it < 4; ++it) {
        const int n = blockIdx.y * 1024 + wid * 128 + it * 32 + lane;
        const size_t off = bhbase + (size_t)n * 64;

        const float* xrow = g_xmid + off;
#pragma unroll
        for (int j = 0; j < 16; ++j) {
            float4 v = *(const float4*)(xrow + 4 * j);
            xw[(4 * j + 0) * 32 + lane] = v.x;
            xw[(4 * j + 1) * 32 + lane] = v.y;
            xw[(4 * j + 2) * 32 + lane] = v.z;
            xw[(4 * j + 3) * 32 + lane] = v.w;
        }
        __syncwarp();

        float w_[64];
        float tacc = 0.f;
#pragma unroll
        for (int gt = 0; gt < 4; ++gt) {
            ull acc[16];
#pragma unroll
            for (int j = 0; j < 16; ++j) acc[j] = *(ull*)&hb[gt * 16 + j];
#pragma unroll 8
            for (int c = 0; c < 64; ++c) {
                float xv = xw[c * 32 + lane];
                ull xp = pk2(xv, xv);
                const ulonglong2* wrow = (const ulonglong2*)(wp4 + c * 32) + gt * 8;
#pragma unroll
                for (int p = 0; p < 8; ++p) {
                    ulonglong2 wv = wrow[p];
                    fma2(acc[2 * p],     xp, wv.x);
                    fma2(acc[2 * p + 1], xp, wv.y);
                }
            }
#pragma unroll
            for (int j = 0; j < 16; ++j) {
                float2 pr = up2(acc[j]);
                tacc += gelu_f(pr.x) * W2s[gt * 16 + j];
                w_[gt * 16 + j] = pr.y;
            }
        }
        __syncwarp();

        float temp = fmaxf(gelu_f(tacc + b2v) + biasv, 0.01f);
        float itmp = 1.f / temp;

        const float* urow = u + off;
        float mx = -1e30f;
#pragma unroll
        for (int j = 0; j < 16; ++j) {
            float4 uv = *(const float4*)(urow + 4 * j);
            float ua[4] = {uv.x, uv.y, uv.z, uv.w};
#pragma unroll
            for (int q = 0; q < 4; ++q) {
                float gn = -__logf(-__logf(ua[q] + 1e-8f) + 1e-8f);
                float z = (w_[4 * j + q] + gn) * itmp;
                w_[4 * j + q] = z;
                mx = fmaxf(mx, z);
            }
        }
        float ssum = 0.f;
#pragma unroll
        for (int g = 0; g < 64; ++g) { float e = __expf(w_[g] - mx); w_[g] = e; ssum += e; }
        float inv = 1.f / ssum;

        float* srow = g_slicew + off;
        __nv_bfloat16* hrow = g_swh + off;
        __nv_bfloat16* lrow = g_swl + off;
#pragma unroll
        for (int j = 0; j < 16; ++j) {
            float v0 = w_[4 * j] * inv, v1 = w_[4 * j + 1] * inv;
            float v2 = w_[4 * j + 2] * inv, v3 = w_[4 * j + 3] * inv;
            *(float4*)(srow + 4 * j) = make_float4(v0, v1, v2, v3);
            float4 fv = make_float4(v0, v1, v2, v3);
            uint2 hp, lp;
            cvt_split4(fv, hp, lp);
            *(uint2*)(hrow + 4 * j) = hp;
            *(uint2*)(lrow + 4 * j) = lp;
        }
    }
}

// ============================================================
// Pooling + norm (unchanged).
// ============================================================
__global__ void __launch_bounds__(256) k_pool()
{
    __shared__ __align__(16) float Xs[64][64];
    __shared__ __align__(16) float Wp[64][64];
    int bh = blockIdx.x, chunk = blockIdx.y;
    int tid = threadIdx.x;
    int c0 = (tid & 15) << 2;
    int g0 = (tid >> 4) << 2;
    float acc[4][4] = {};
    float nacc[4] = {0.f, 0.f, 0.f, 0.f};
    size_t base = (size_t)bh * N_ * 64 + (size_t)chunk * 512 * 64;

    for (int t0 = 0; t0 < 512; t0 += 64) {
#pragma unroll
        for (int it = 0; it < 4; ++it) {
            int v = tid + (it << 8);
            int rr = v >> 4, cc = (v & 15) << 2;
            *(float4*)&Xs[rr][cc] = *(const float4*)&g_xmid  [base + (size_t)(t0 + rr) * 64 + cc];
            *(float4*)&Wp[rr][cc] = *(const float4*)&g_slicew[base + (size_t)(t0 + rr) * 64 + cc];
        }
        __syncthreads();
#pragma unroll
        for (int tt2 = 0; tt2 < 64; ++tt2) {
            float4 xv = *(const float4*)&Xs[tt2][c0];
            float4 wv = *(const float4*)&Wp[tt2][g0];
            float xa[4] = {xv.x, xv.y, xv.z, xv.w};
            float wa[4] = {wv.x, wv.y, wv.z, wv.w};
#pragma unroll
            for (int j = 0; j < 4; ++j) {
                nacc[j] += wa[j];
#pragma unroll
                for (int i = 0; i < 4; ++i) acc[j][i] += wa[j] * xa[i];
            }
        }
        __syncthreads();
    }
#pragma unroll
    for (int j = 0; j < 4; ++j) {
#pragma unroll
        for (int i = 0; i < 4; ++i)
            atomicAdd(&g_tok[bh * 4096 + (g0 + j) * 64 + (c0 + i)], acc[j][i]);
        if (c0 == 0) atomicAdd(&g_norm[bh * 64 + g0 + j], nacc[j]);
    }
}

// ============================================================
// Slice attention (unchanged).
// ============================================================
__global__ void __launch_bounds__(64) k_attn(const float* __restrict__ Wq,
                                             const float* __restrict__ Wk,
                                             const float* __restrict__ Wv)
{
    __shared__ float T [64 * 65];
    __shared__ float Ks[64 * 64];
    int bh = blockIdx.x, tid = threadIdx.x;

    for (int i = tid; i < 4096; i += 64) {
        int g = i >> 6, c = i & 63;
        T[g * 65 + c] = g_tok[bh * 4096 + i] / (g_norm[bh * 64 + g] + 1e-5f);
    }
    __syncthreads();

    int g = tid;
    float q[64];
    for (int c = 0; c < 64; ++c) {
        float s0 = 0.f, s1 = 0.f;
        for (int k = 0; k < 64; k += 2) {
            s0 += T[g * 65 + k]     * Wq[c * 64 + k];
            s1 += T[g * 65 + k + 1] * Wq[c * 64 + k + 1];
        }
        q[c] = s0 + s1;
    }
    for (int c = 0; c < 64; ++c) {
        float s0 = 0.f, s1 = 0.f;
        for (int k = 0; k < 64; k += 2) {
            s0 += T[g * 65 + k]     * Wk[c * 64 + k];
            s1 += T[g * 65 + k + 1] * Wk[c * 64 + k + 1];
        }
        Ks[g * 64 + c] = s0 + s1;
    }
    __syncthreads();

    float sc[64];
    for (int j = 0; j < 64; ++j) {
        float s0 = 0.f, s1 = 0.f;
        for (int c = 0; c < 64; c += 2) {
            s0 += q[c]     * Ks[j * 64 + c];
            s1 += q[c + 1] * Ks[j * 64 + c + 1];
        }
        sc[j] = (s0 + s1) * 0.125f;
    }
    float mx = -1e30f;
    for (int j = 0; j < 64; ++j) mx = fmaxf(mx, sc[j]);
    float sum = 0.f;
    for (int j = 0; j < 64; ++j) { sc[j] = expf(sc[j] - mx); sum += sc[j]; }
    float inv = 1.f / sum;

    float pv[64];
    for (int c = 0; c < 64; ++c) {
        float s0 = 0.f, s1 = 0.f;
        for (int j = 0; j < 64; j += 2) {
            s0 += sc[j]     * T[j * 65 + c];
            s1 += sc[j + 1] * T[(j + 1) * 65 + c];
        }
        pv[c] = (s0 + s1) * inv;
    }
    for (int c = 0; c < 64; ++c) {
        float s0 = 0.f, s1 = 0.f;
        for (int k = 0; k < 64; k += 2) {
            s0 += pv[k]     * Wv[c * 64 + k];
            s1 += pv[k + 1] * Wv[c * 64 + k + 1];
        }
        g_outs[bh * 4096 + g * 64 + c] = s0 + s1;
    }
}

// ============================================================
// P[b][d][h*64+g] = sum_c outs[bh][g][c] * Wo[d][h*64+c]
// -> written directly as split-bf16 (g_ph/g_pl).
// ============================================================
__global__ void __launch_bounds__(256) k_pmat(const float* __restrict__ Wo)
{
    __shared__ float os [64][65];
    __shared__ float wsm[64][64];
    int bh = blockIdx.x, b = bh >> 3, h = bh & 7, tid = threadIdx.x;
    for (int i = tid; i < 4096; i += 256) os[i >> 6][i & 63] = g_outs[bh * 4096 + i];
    int g = tid & 63, dl = tid >> 6;

    for (int tile = 0; tile < 4; ++tile) {
        __syncthreads();
        for (int i = tid; i < 4096; i += 256) {
            int dr = i >> 6, c = i & 63;
            wsm[dr][c] = Wo[(size_t)(tile * 64 + dr) * 512 + h * 64 + c];
        }
        __syncthreads();
#pragma unroll
        for (int ds = 0; ds < 16; ++ds) {
            int dloc = dl * 16 + ds;
            float s = 0.f;
#pragma unroll 8
            for (int c = 0; c < 64; ++c) s += wsm[dloc][c] * os[g][c];
            size_t idx = ((size_t)b * 256 + tile * 64 + dloc) * 512 + h * 64 + g;
            __nv_bfloat16 hv = __float2bfloat16(s);
            g_ph[idx] = hv;
            g_pl[idx] = __float2bfloat16(s - __bfloat162float(hv));
        }
    }
}

// ============================================================
extern "C" void kernel_launch(void* const* d_in, const int* in_sizes, int n_in,
                              void* d_out, int out_size)
{
    const float* x    = (const float*)d_in[0];
    const float* Wx   = (const float*)d_in[1];
    const float* bx   = (const float*)d_in[2];
    const float* W1   = (const float*)d_in[3];
    const float* b1   = (const float*)d_in[4];
    const float* W2   = (const float*)d_in[5];
    const float* b2   = (const float*)d_in[6];
    const float* bias = (const float*)d_in[7];
    const float* Ws   = (const float*)d_in[8];
    const float* bs   = (const float*)d_in[9];
    const float* Wq   = (const float*)d_in[10];
    const float* Wk   = (const float*)d_in[11];
    const float* Wv   = (const float*)d_in[12];
    const float* Wo   = (const float*)d_in[13];
    const float* bo   = (const float*)d_in[14];
    const float* u    = (const float*)d_in[15];
    float* out = (float*)d_out;

    static void *p_xh, *p_xl, *p_wxh, *p_wxl, *p_swh, *p_swl, *p_ph, *p_pl;
    static int init_done = 0;
    if (!init_done) {
        cudaFuncSetAttribute(k_route, cudaFuncAttributeMaxDynamicSharedMemorySize, 99072);
        cudaFuncSetAttribute(k_gemm_tc<256, 1>, cudaFuncAttributeMaxDynamicSharedMemorySize, SM_TC_TOTAL);
        cudaFuncSetAttribute(k_gemm_tc<512, 2>, cudaFuncAttributeMaxDynamicSharedMemorySize, SM_TC_TOTAL);
        cudaGetSymbolAddress(&p_xh,  g_xh);  cudaGetSymbolAddress(&p_xl,  g_xl);
        cudaGetSymbolAddress(&p_wxh, g_wxh); cudaGetSymbolAddress(&p_wxl, g_wxl);
        cudaGetSymbolAddress(&p_swh, g_swh); cudaGetSymbolAddress(&p_swl, g_swl);
        cudaGetSymbolAddress(&p_ph,  g_ph);  cudaGetSymbolAddress(&p_pl,  g_pl);
        init_done = 1;
    }

    k_zero<<<512, 256>>>();
    k_cvt<<<8192, 256>>>(x,  (__nv_bfloat16*)p_xh,  (__nv_bfloat16*)p_xl,  (M_ * D_) / 8);
    k_cvt<<<64,   256>>>(Wx, (__nv_bfloat16*)p_wxh, (__nv_bfloat16*)p_wxl, (INNER_ * D_) / 8);
    k_gemm_tc<256, 1><<<dim3(4, 512), 256, SM_TC_TOTAL>>>(
        (const __nv_bfloat16*)p_xh, (const __nv_bfloat16*)p_xl,
        (const __nv_bfloat16*)p_wxh, (const __nv_bfloat16*)p_wxl, bx, nullptr);
    k_route<<<dim3(32, 16), 256, 99072>>>(u, W1, b1, W2, b2, bias, Ws, bs);
    k_pool<<<dim3(32, 32), 256>>>();
    k_attn<<<32, 64>>>(Wq, Wk, Wv);
    k_pmat<<<32, 256>>>(Wo);
    k_gemm_tc<512, 2><<<dim3(2, 512), 256, SM_TC_TOTAL>>>(
        (const __nv_bfloat16*)p_swh, (const __nv_bfloat16*)p_swl,
        (const __nv_bfloat16*)p_ph, (const __nv_bfloat16*)p_pl, bo, out);
}

// round 13
// speedup vs baseline: 2.7896x; 1.1213x over previous
#include <cuda_runtime.h>
#include <cuda_bf16.h>
#include <cstdint>
#include <math.h>

#define B_     4
#define N_     16384
#define D_     256
#define H_     8
#define DH_    64
#define G_     64
#define INNER_ 512
#define BH_    32
#define M_     65536

typedef unsigned long long ull;

// ---- scratch ----
__device__ float g_xmid  [(size_t)BH_ * N_ * DH_];   // [B,H,N,DH]
__device__ float g_slicew[(size_t)BH_ * N_ * G_];    // [B,H,N,G] fp32 (pool)
__device__ float g_norm  [BH_ * G_];
__device__ float g_tok   [BH_ * G_ * DH_];
__device__ float g_outs  [BH_ * G_ * DH_];
// bf16 split operands for HMMA GEMMs
__device__ __nv_bfloat16 g_xh [(size_t)M_ * D_],        g_xl [(size_t)M_ * D_];
__device__ __nv_bfloat16 g_wxh[INNER_ * D_],            g_wxl[INNER_ * D_];
__device__ __nv_bfloat16 g_swh[(size_t)BH_ * N_ * G_],  g_swl[(size_t)BH_ * N_ * G_];
__device__ __nv_bfloat16 g_ph [B_ * D_ * INNER_],       g_pl [B_ * D_ * INNER_];

__device__ __forceinline__ ull pk2(float lo, float hi) {
    ull r; asm("mov.b64 %0, {%1,%2};" : "=l"(r) : "f"(lo), "f"(hi)); return r;
}
__device__ __forceinline__ void fma2(ull& d, ull a, ull b) {
    asm("fma.rn.f32x2 %0, %1, %2, %0;" : "+l"(d) : "l"(a), "l"(b));
}
__device__ __forceinline__ float2 up2(ull v) {
    float2 r; asm("mov.b64 {%0,%1}, %2;" : "=f"(r.x), "=f"(r.y) : "l"(v)); return r;
}
__device__ __forceinline__ float gelu_f(float x) {
    return 0.5f * x * (1.0f + erff(x * 0.70710678118654752f));
}
__device__ __forceinline__ uint32_t smem_u32(const void* p) {
    uint32_t a; asm("{ .reg .u64 t; cvta.to.shared.u64 t, %1; cvt.u32.u64 %0, t; }"
                    : "=r"(a) : "l"(p));
    return a;
}

// ---- warp-level tensor ops (base target; NO tcgen05 on compute_103) ----
__device__ __forceinline__ void ldsm4(uint32_t& r0, uint32_t& r1, uint32_t& r2,
                                      uint32_t& r3, uint32_t addr) {
    asm volatile("ldmatrix.sync.aligned.m8n8.x4.shared.b16 {%0,%1,%2,%3}, [%4];"
                 : "=r"(r0), "=r"(r1), "=r"(r2), "=r"(r3) : "r"(addr));
}
__device__ __forceinline__ void mma16816(float* c, const uint32_t* a,
                                         uint32_t b0, uint32_t b1) {
    asm volatile("mma.sync.aligned.m16n8k16.row.col.f32.bf16.bf16.f32 "
                 "{%0,%1,%2,%3}, {%4,%5,%6,%7}, {%8,%9}, {%0,%1,%2,%3};"
                 : "+f"(c[0]), "+f"(c[1]), "+f"(c[2]), "+f"(c[3])
                 : "r"(a[0]), "r"(a[1]), "r"(a[2]), "r"(a[3]), "r"(b0), "r"(b1));
}
__device__ __forceinline__ void cpa16(uint32_t dst, const void* src) {
    asm volatile("cp.async.cg.shared.global [%0], [%1], 16;" :: "r"(dst), "l"(src));
}
#define CP_COMMIT() asm volatile("cp.async.commit_group;" ::: "memory")
#define CP_WAIT(n)  asm volatile("cp.async.wait_group %0;" :: "n"(n) : "memory")

// per-stage smem (512-thr GEMM): Ah 16K | Al 16K | Bh 32K | Bl 32K. 2 stages.
#define SM_STAGE   98304
#define SM_TC_TOTAL 196608

__device__ __forceinline__ void cvt_split4(float4 v, uint2& hi, uint2& lo) {
    __nv_bfloat16 hx = __float2bfloat16(v.x), hy = __float2bfloat16(v.y);
    __nv_bfloat16 hz = __float2bfloat16(v.z), hw = __float2bfloat16(v.w);
    __nv_bfloat16 lx = __float2bfloat16(v.x - __bfloat162float(hx));
    __nv_bfloat16 ly = __float2bfloat16(v.y - __bfloat162float(hy));
    __nv_bfloat16 lz = __float2bfloat16(v.z - __bfloat162float(hz));
    __nv_bfloat16 lw = __float2bfloat16(v.w - __bfloat162float(hw));
    hi.x = (uint32_t)__bfloat16_as_ushort(hx) | ((uint32_t)__bfloat16_as_ushort(hy) << 16);
    hi.y = (uint32_t)__bfloat16_as_ushort(hz) | ((uint32_t)__bfloat16_as_ushort(hw) << 16);
    lo.x = (uint32_t)__bfloat16_as_ushort(lx) | ((uint32_t)__bfloat16_as_ushort(ly) << 16);
    lo.y = (uint32_t)__bfloat16_as_ushort(lz) | ((uint32_t)__bfloat16_as_ushort(lw) << 16);
}

// ============================================================
__global__ void k_zero() {
    int i = blockIdx.x * 256 + threadIdx.x;
    if (i < BH_ * G_)        g_norm[i] = 0.f;
    if (i < BH_ * G_ * DH_)  g_tok[i]  = 0.f;
}

// ============================================================
// fp32 -> split-bf16 pre-conversion (8 elements/thread)
// ============================================================
__global__ void __launch_bounds__(256) k_cvt(const float* __restrict__ src,
                                             __nv_bfloat16* __restrict__ dh,
                                             __nv_bfloat16* __restrict__ dl, int n8)
{
    int i = blockIdx.x * 256 + threadIdx.x;
    if (i >= n8) return;
    const float4* s = (const float4*)src + 2 * (size_t)i;
    float4 v0 = s[0], v1 = s[1];
    uint2 h0, l0, h1, l1;
    cvt_split4(v0, h0, l0); cvt_split4(v1, h1, l1);
    ((uint4*)dh)[i] = make_uint4(h0.x, h0.y, h1.x, h1.y);
    ((uint4*)dl)[i] = make_uint4(l0.x, l0.y, l1.x, l1.y);
}

// ============================================================
// Split-bf16 HMMA GEMM, 512 threads, tile 128x256, 16 warps 4x4,
// cp.async 2-stage. K chunks of 64.
// MODE 1: A=g_xh/l [M][K], B=g_wxh/l rows, C scattered to g_xmid.
// MODE 2: A gathered from g_swh/l (k=h*64+g), B=g_ph/l[b], C plain.
// ============================================================
template<int KTOT, int MODE>
__global__ void __launch_bounds__(512)
k_gemm_tc(const __nv_bfloat16* __restrict__ Ah, const __nv_bfloat16* __restrict__ Al,
          const __nv_bfloat16* __restrict__ Bh, const __nv_bfloat16* __restrict__ Bl,
          const float* __restrict__ bias, float* __restrict__ C)
{
    extern __shared__ __align__(1024) char sm_[];
    const uint32_t smb = smem_u32(sm_);
    const int tid  = threadIdx.x;
    const int wid  = tid >> 5;
    const int lane = tid & 31;
    const int gm0  = blockIdx.y << 7;
    const int gn0  = blockIdx.x << 8;          // 256-wide N tile
    const int b_idx = gm0 >> 14;
    const int wm = (wid >> 2) << 5;            // 0,32,64,96
    const int wn = (wid & 3)  << 6;            // 0,64,128,192

    float acc[2][8][4];
#pragma unroll
    for (int i = 0; i < 2; ++i)
#pragma unroll
        for (int j = 0; j < 8; ++j)
#pragma unroll
            for (int q = 0; q < 4; ++q) acc[i][j][q] = 0.f;

    const int a_row = (lane & 15);
    const int a_chk = (lane >> 4) << 4;
    const int b_row = (lane & 7) + (((lane >> 4) & 1) << 3);
    const int b_chk = ((lane >> 3) & 1) << 4;
    const int NCH = KTOT / 64;

    auto prefetch = [&](int ch, int stage) {
        const int k0 = ch << 6;
        const uint32_t sb = smb + stage * SM_STAGE;
        // A bufs: 128 rows x 64 cols bf16 = 1024 x 16B each
#pragma unroll
        for (int i = 0; i < 2; ++i) {
            const __nv_bfloat16* base = (i == 0) ? Ah : Al;
#pragma unroll
            for (int t = 0; t < 2; ++t) {
                int j = tid + (t << 9);        // 0..1023
                int row = j >> 3, cc = j & 7;
                uint32_t off = (row << 7) + (cc << 4);
                uint32_t sw  = off ^ ((off >> 3) & 0x70);
                const __nv_bfloat16* src;
                if (MODE == 2) {
                    int m = gm0 + row, n = m & (N_ - 1);
                    int h = k0 >> 6;
                    src = base + ((size_t)((b_idx << 3) + h) * N_ + n) * 64 + (cc << 3);
                } else {
                    src = base + (size_t)(gm0 + row) * KTOT + k0 + (cc << 3);
                }
                cpa16(sb + (i << 14) + sw, src);
            }
        }
        // B bufs: 256 rows x 64 cols bf16 = 2048 x 16B each
#pragma unroll
        for (int i = 0; i < 2; ++i) {
            const __nv_bfloat16* base = (i == 0) ? Bh : Bl;
#pragma unroll
            for (int t = 0; t < 4; ++t) {
                int j = tid + (t << 9);        // 0..2047
                int row = j >> 3, cc = j & 7;
                uint32_t off = (row << 7) + (cc << 4);
                uint32_t sw  = off ^ ((off >> 3) & 0x70);
                const __nv_bfloat16* src;
                if (MODE == 2)
                    src = base + ((size_t)b_idx * 256 + gn0 + row) * 512 + k0 + (cc << 3);
                else
                    src = base + (size_t)(gn0 + row) * KTOT + k0 + (cc << 3);
                cpa16(sb + 32768 + (i << 15) + sw, src);
            }
        }
    };

    prefetch(0, 0); CP_COMMIT();
    int stage = 0;
    for (int ch = 0; ch < NCH; ++ch) {
        if (ch + 1 < NCH) { prefetch(ch + 1, stage ^ 1); CP_COMMIT(); CP_WAIT(1); }
        else              { CP_WAIT(0); }
        __syncthreads();

        const uint32_t sb = smb + stage * SM_STAGE;
#pragma unroll
        for (int ks = 0; ks < 4; ++ks) {
            const int kb = ks << 5;
            uint32_t ah[2][4], al[2][4];
#pragma unroll
            for (int mt = 0; mt < 2; ++mt) {
                uint32_t bo = ((wm + (mt << 4) + a_row) << 7) + kb + a_chk;
                uint32_t sw = bo ^ ((bo >> 3) & 0x70);
                ldsm4(ah[mt][0], ah[mt][1], ah[mt][2], ah[mt][3], sb + sw);
                ldsm4(al[mt][0], al[mt][1], al[mt][2], al[mt][3], sb + 16384 + sw);
            }
#pragma unroll
            for (int p2 = 0; p2 < 4; ++p2) {
                uint32_t bo = ((wn + (p2 << 4) + b_row) << 7) + kb + b_chk;
                uint32_t sw = bo ^ ((bo >> 3) & 0x70);
                uint32_t bh0, bh1, bh2, bh3, bl0, bl1, bl2, bl3;
                ldsm4(bh0, bh1, bh2, bh3, sb + 32768 + sw);
                ldsm4(bl0, bl1, bl2, bl3, sb + 65536 + sw);
#pragma unroll
                for (int mt = 0; mt < 2; ++mt) {
                    mma16816(acc[mt][2 * p2],     ah[mt], bh0, bh1);
                    mma16816(acc[mt][2 * p2 + 1], ah[mt], bh2, bh3);
                    mma16816(acc[mt][2 * p2],     ah[mt], bl0, bl1);
                    mma16816(acc[mt][2 * p2 + 1], ah[mt], bl2, bl3);
                    mma16816(acc[mt][2 * p2],     al[mt], bh0, bh1);
                    mma16816(acc[mt][2 * p2 + 1], al[mt], bh2, bh3);
                }
            }
        }
        __syncthreads();
        stage ^= 1;
    }

    // ---- epilogue ----
    const int grp = lane >> 2, qid = (lane & 3) << 1;
#pragma unroll
    for (int mt = 0; mt < 2; ++mt) {
#pragma unroll
        for (int nt = 0; nt < 8; ++nt) {
            int col = gn0 + wn + (nt << 3) + qid;
            float bv0 = bias[col], bv1 = bias[col + 1];
            int r0 = gm0 + wm + (mt << 4) + grp;
            float2 v0 = make_float2(acc[mt][nt][0] + bv0, acc[mt][nt][1] + bv1);
            float2 v1 = make_float2(acc[mt][nt][2] + bv0, acc[mt][nt][3] + bv1);
            if (MODE == 1) {
                int bb = r0 >> 14, n = r0 & (N_ - 1);
                int h = col >> 6, c = col & 63;
                float* d0 = g_xmid + (((size_t)((bb << 3) + h) * N_ + n) << 6) + c;
                *(float2*)d0 = v0;
                *(float2*)(d0 + (8 << 6)) = v1;
            } else {
                float* d0 = C + (size_t)r0 * 256 + col;
                *(float2*)d0 = v0;
                *(float2*)(d0 + (size_t)8 * 256) = v1;
            }
        }
    }
}

// ============================================================
// Routing, lane-per-token, ALL gmem coalesced via per-warp
// smem staging (stride-33 transposed tiles).
// smem: wp4 32768 | xu 8*8448 | hb 512 | W2s 256 = 101120B
// ============================================================
#define RT_SMEM 101120
__global__ void __launch_bounds__(256, 2) k_route(const float* __restrict__ u,
    const float* __restrict__ W1, const float* __restrict__ b1,
    const float* __restrict__ W2, const float* __restrict__ b2,
    const float* __restrict__ biasH, const float* __restrict__ Ws,
    const float* __restrict__ bs)
{
    extern __shared__ __align__(1024) char sm_[];
    float4* wp4 = (float4*)sm_;
    float*  xsf = (float*)(sm_ + 32768);
    float2* hb  = (float2*)(sm_ + 32768 + 67584);
    float*  W2s = (float*)(sm_ + 32768 + 67584 + 512);

    const int bh   = blockIdx.x;
    const int tid  = threadIdx.x;
    const int wid  = tid >> 5;
    const int lane = tid & 31;

    for (int i = tid; i < 2048; i += 256) {
        int c = i >> 5, p = i & 31;
        wp4[c * 32 + p] = make_float4(W1[(2 * p) * 64 + c],     Ws[(2 * p) * 64 + c],
                                      W1[(2 * p + 1) * 64 + c], Ws[(2 * p + 1) * 64 + c]);
    }
    if (tid < 64) { hb[tid] = make_float2(b1[tid], bs[tid]); W2s[tid] = W2[tid]; }
    __syncthreads();

    const float b2v   = b2[0];
    const float biasv = biasH[bh & 7];
    const size_t bhbase = (size_t)bh * N_ * 64;
    float* xu = xsf + wid * 2112;              // 64*33 floats per warp

    for (int it = 0; it < 4; ++it) {
        const int t0 = blockIdx.y * 1024 + wid * 128 + it * 32;

        // ---- stage x tile coalesced -> transposed smem [c][33] ----
        const float* xbase = g_xmid + bhbase + (size_t)t0 * 64;
#pragma unroll
        for (int k = 0; k < 16; ++k) {
            int fid = lane + (k << 5);
            int row = fid >> 4, c4 = fid & 15;
            float4 v = *(const float4*)(xbase + row * 64 + (c4 << 2));
            xu[(4 * c4 + 0) * 33 + row] = v.x;
            xu[(4 * c4 + 1) * 33 + row] = v.y;
            xu[(4 * c4 + 2) * 33 + row] = v.z;
            xu[(4 * c4 + 3) * 33 + row] = v.w;
        }
        __syncwarp();

        // ---- matvec: hidden (w/ b1) and logits (w/ bs) via FFMA2 ----
        float w_[64];
        float tacc = 0.f;
#pragma unroll
        for (int gt = 0; gt < 4; ++gt) {
            ull acc[16];
#pragma unroll
            for (int j = 0; j < 16; ++j) acc[j] = *(ull*)&hb[gt * 16 + j];
#pragma unroll 8
            for (int c = 0; c < 64; ++c) {
                float xv = xu[c * 33 + lane];
                ull xp = pk2(xv, xv);
                const ulonglong2* wrow = (const ulonglong2*)(wp4 + c * 32) + gt * 8;
#pragma unroll
                for (int p = 0; p < 8; ++p) {
                    ulonglong2 wv = wrow[p];
                    fma2(acc[2 * p],     xp, wv.x);
                    fma2(acc[2 * p + 1], xp, wv.y);
                }
            }
#pragma unroll
            for (int j = 0; j < 16; ++j) {
                float2 pr = up2(acc[j]);
                tacc += gelu_f(pr.x) * W2s[gt * 16 + j];
                w_[gt * 16 + j] = pr.y;
            }
        }
        __syncwarp();

        float temp = fmaxf(gelu_f(tacc + b2v) + biasv, 0.01f);
        float itmp = 1.f / temp;

        // ---- stage u tile coalesced (reuse xu) ----
        const float* ubase = u + bhbase + (size_t)t0 * 64;
#pragma unroll
        for (int k = 0; k < 16; ++k) {
            int fid = lane + (k << 5);
            int row = fid >> 4, c4 = fid & 15;
            float4 v = *(const float4*)(ubase + row * 64 + (c4 << 2));
            xu[(4 * c4 + 0) * 33 + row] = v.x;
            xu[(4 * c4 + 1) * 33 + row] = v.y;
            xu[(4 * c4 + 2) * 33 + row] = v.z;
            xu[(4 * c4 + 3) * 33 + row] = v.w;
        }
        __syncwarp();

        // ---- gumbel-softmax (per-lane token) ----
        float mx = -1e30f;
#pragma unroll
        for (int g = 0; g < 64; ++g) {
            float uu = xu[g * 33 + lane];
            float gn = -__logf(-__logf(uu + 1e-8f) + 1e-8f);
            float z = (w_[g] + gn) * itmp;
            w_[g] = z;
            mx = fmaxf(mx, z);
        }
        float ssum = 0.f;
#pragma unroll
        for (int g = 0; g < 64; ++g) { float e = __expf(w_[g] - mx); w_[g] = e; ssum += e; }
        float inv = 1.f / ssum;
        __syncwarp();

        // ---- write normalized weights back to smem [g][33] ----
#pragma unroll
        for (int g = 0; g < 64; ++g) xu[g * 33 + lane] = w_[g] * inv;
        __syncwarp();

        // ---- cooperative coalesced stores: fp32 + bf16 hi/lo ----
        float* swbase = g_slicew + bhbase + (size_t)t0 * 64;
        __nv_bfloat16* hbase = g_swh + bhbase + (size_t)t0 * 64;
        __nv_bfloat16* lbase = g_swl + bhbase + (size_t)t0 * 64;
#pragma unroll
        for (int k = 0; k < 16; ++k) {
            int fid = lane + (k << 5);
            int row = fid >> 4, c4 = fid & 15;
            float4 v = make_float4(xu[(4 * c4 + 0) * 33 + row],
                                   xu[(4 * c4 + 1) * 33 + row],
                                   xu[(4 * c4 + 2) * 33 + row],
                                   xu[(4 * c4 + 3) * 33 + row]);
            *(float4*)(swbase + row * 64 + (c4 << 2)) = v;
            uint2 hp, lp;
            cvt_split4(v, hp, lp);
            *(uint2*)(hbase + row * 64 + (c4 << 2)) = hp;
            *(uint2*)(lbase + row * 64 + (c4 << 2)) = lp;
        }
        __syncwarp();
    }
}

// ============================================================
// Pooling + norm (unchanged).
// ============================================================
__global__ void __launch_bounds__(256) k_pool()
{
    __shared__ __align__(16) float Xs[64][64];
    __shared__ __align__(16) float Wp[64][64];
    int bh = blockIdx.x, chunk = blockIdx.y;
    int tid = threadIdx.x;
    int c0 = (tid & 15) << 2;
    int g0 = (tid >> 4) << 2;
    float acc[4][4] = {};
    float nacc[4] = {0.f, 0.f, 0.f, 0.f};
    size_t base = (size_t)bh * N_ * 64 + (size_t)chunk * 512 * 64;

    for (int t0 = 0; t0 < 512; t0 += 64) {
#pragma unroll
        for (int it = 0; it < 4; ++it) {
            int v = tid + (it << 8);
            int rr = v >> 4, cc = (v & 15) << 2;
            *(float4*)&Xs[rr][cc] = *(const float4*)&g_xmid  [base + (size_t)(t0 + rr) * 64 + cc];
            *(float4*)&Wp[rr][cc] = *(const float4*)&g_slicew[base + (size_t)(t0 + rr) * 64 + cc];
        }
        __syncthreads();
#pragma unroll
        for (int tt2 = 0; tt2 < 64; ++tt2) {
            float4 xv = *(const float4*)&Xs[tt2][c0];
            float4 wv = *(const float4*)&Wp[tt2][g0];
            float xa[4] = {xv.x, xv.y, xv.z, xv.w};
            float wa[4] = {wv.x, wv.y, wv.z, wv.w};
#pragma unroll
            for (int j = 0; j < 4; ++j) {
                nacc[j] += wa[j];
#pragma unroll
                for (int i = 0; i < 4; ++i) acc[j][i] += wa[j] * xa[i];
            }
        }
        __syncthreads();
    }
#pragma unroll
    for (int j = 0; j < 4; ++j) {
#pragma unroll
        for (int i = 0; i < 4; ++i)
            atomicAdd(&g_tok[bh * 4096 + (g0 + j) * 64 + (c0 + i)], acc[j][i]);
        if (c0 == 0) atomicAdd(&g_norm[bh * 64 + g0 + j], nacc[j]);
    }
}

// ============================================================
// Slice attention (unchanged).
// ============================================================
__global__ void __launch_bounds__(64) k_attn(const float* __restrict__ Wq,
                                             const float* __restrict__ Wk,
                                             const float* __restrict__ Wv)
{
    __shared__ float T [64 * 65];
    __shared__ float Ks[64 * 64];
    int bh = blockIdx.x, tid = threadIdx.x;

    for (int i = tid; i < 4096; i += 64) {
        int g = i >> 6, c = i & 63;
        T[g * 65 + c] = g_tok[bh * 4096 + i] / (g_norm[bh * 64 + g] + 1e-5f);
    }
    __syncthreads();

    int g = tid;
    float q[64];
    for (int c = 0; c < 64; ++c) {
        float s0 = 0.f, s1 = 0.f;
        for (int k = 0; k < 64; k += 2) {
            s0 += T[g * 65 + k]     * Wq[c * 64 + k];
            s1 += T[g * 65 + k + 1] * Wq[c * 64 + k + 1];
        }
        q[c] = s0 + s1;
    }
    for (int c = 0; c < 64; ++c) {
        float s0 = 0.f, s1 = 0.f;
        for (int k = 0; k < 64; k += 2) {
            s0 += T[g * 65 + k]     * Wk[c * 64 + k];
            s1 += T[g * 65 + k + 1] * Wk[c * 64 + k + 1];
        }
        Ks[g * 64 + c] = s0 + s1;
    }
    __syncthreads();

    float sc[64];
    for (int j = 0; j < 64; ++j) {
        float s0 = 0.f, s1 = 0.f;
        for (int c = 0; c < 64; c += 2) {
            s0 += q[c]     * Ks[j * 64 + c];
            s1 += q[c + 1] * Ks[j * 64 + c + 1];
        }
        sc[j] = (s0 + s1) * 0.125f;
    }
    float mx = -1e30f;
    for (int j = 0; j < 64; ++j) mx = fmaxf(mx, sc[j]);
    float sum = 0.f;
    for (int j = 0; j < 64; ++j) { sc[j] = expf(sc[j] - mx); sum += sc[j]; }
    float inv = 1.f / sum;

    float pv[64];
    for (int c = 0; c < 64; ++c) {
        float s0 = 0.f, s1 = 0.f;
        for (int j = 0; j < 64; j += 2) {
            s0 += sc[j]     * T[j * 65 + c];
            s1 += sc[j + 1] * T[(j + 1) * 65 + c];
        }
        pv[c] = (s0 + s1) * inv;
    }
    for (int c = 0; c < 64; ++c) {
        float s0 = 0.f, s1 = 0.f;
        for (int k = 0; k < 64; k += 2) {
            s0 += pv[k]     * Wv[c * 64 + k];
            s1 += pv[k + 1] * Wv[c * 64 + k + 1];
        }
        g_outs[bh * 4096 + g * 64 + c] = s0 + s1;
    }
}

// ============================================================
// P[b][d][h*64+g] = sum_c outs[bh][g][c] * Wo[d][h*64+c]
// written directly as split-bf16.
// ============================================================
__global__ void __launch_bounds__(256) k_pmat(const float* __restrict__ Wo)
{
    __shared__ float os [64][65];
    __shared__ float wsm[64][64];
    int bh = blockIdx.x, b = bh >> 3, h = bh & 7, tid = threadIdx.x;
    for (int i = tid; i < 4096; i += 256) os[i >> 6][i & 63] = g_outs[bh * 4096 + i];
    int g = tid & 63, dl = tid >> 6;

    for (int tile = 0; tile < 4; ++tile) {
        __syncthreads();
        for (int i = tid; i < 4096; i += 256) {
            int dr = i >> 6, c = i & 63;
            wsm[dr][c] = Wo[(size_t)(tile * 64 + dr) * 512 + h * 64 + c];
        }
        __syncthreads();
#pragma unroll
        for (int ds = 0; ds < 16; ++ds) {
            int dloc = dl * 16 + ds;
            float s = 0.f;
#pragma unroll 8
            for (int c = 0; c < 64; ++c) s += wsm[dloc][c] * os[g][c];
            size_t idx = ((size_t)b * 256 + tile * 64 + dloc) * 512 + h * 64 + g;
            __nv_bfloat16 hv = __float2bfloat16(s);
            g_ph[idx] = hv;
            g_pl[idx] = __float2bfloat16(s - __bfloat162float(hv));
        }
    }
}

// ============================================================
extern "C" void kernel_launch(void* const* d_in, const int* in_sizes, int n_in,
                              void* d_out, int out_size)
{
    const float* x    = (const float*)d_in[0];
    const float* Wx   = (const float*)d_in[1];
    const float* bx   = (const float*)d_in[2];
    const float* W1   = (const float*)d_in[3];
    const float* b1   = (const float*)d_in[4];
    const float* W2   = (const float*)d_in[5];
    const float* b2   = (const float*)d_in[6];
    const float* bias = (const float*)d_in[7];
    const float* Ws   = (const float*)d_in[8];
    const float* bs   = (const float*)d_in[9];
    const float* Wq   = (const float*)d_in[10];
    const float* Wk   = (const float*)d_in[11];
    const float* Wv   = (const float*)d_in[12];
    const float* Wo   = (const float*)d_in[13];
    const float* bo   = (const float*)d_in[14];
    const float* u    = (const float*)d_in[15];
    float* out = (float*)d_out;

    static void *p_xh, *p_xl, *p_wxh, *p_wxl, *p_swh, *p_swl, *p_ph, *p_pl;
    static int init_done = 0;
    if (!init_done) {
        cudaFuncSetAttribute(k_route, cudaFuncAttributeMaxDynamicSharedMemorySize, RT_SMEM);
        cudaFuncSetAttribute(k_gemm_tc<256, 1>, cudaFuncAttributeMaxDynamicSharedMemorySize, SM_TC_TOTAL);
        cudaFuncSetAttribute(k_gemm_tc<512, 2>, cudaFuncAttributeMaxDynamicSharedMemorySize, SM_TC_TOTAL);
        cudaGetSymbolAddress(&p_xh,  g_xh);  cudaGetSymbolAddress(&p_xl,  g_xl);
        cudaGetSymbolAddress(&p_wxh, g_wxh); cudaGetSymbolAddress(&p_wxl, g_wxl);
        cudaGetSymbolAddress(&p_swh, g_swh); cudaGetSymbolAddress(&p_swl, g_swl);
        cudaGetSymbolAddress(&p_ph,  g_ph);  cudaGetSymbolAddress(&p_pl,  g_pl);
        init_done = 1;
    }

    k_zero<<<512, 256>>>();
    k_cvt<<<8192, 256>>>(x,  (__nv_bfloat16*)p_xh,  (__nv_bfloat16*)p_xl,  (M_ * D_) / 8);
    k_cvt<<<64,   256>>>(Wx, (__nv_bfloat16*)p_wxh, (__nv_bfloat16*)p_wxl, (INNER_ * D_) / 8);
    k_gemm_tc<256, 1><<<dim3(2, 512), 512, SM_TC_TOTAL>>>(
        (const __nv_bfloat16*)p_xh, (const __nv_bfloat16*)p_xl,
        (const __nv_bfloat16*)p_wxh, (const __nv_bfloat16*)p_wxl, bx, nullptr);
    k_route<<<dim3(32, 16), 256, RT_SMEM>>>(u, W1, b1, W2, b2, bias, Ws, bs);
    k_pool<<<dim3(32, 32), 256>>>();
    k_attn<<<32, 64>>>(Wq, Wk, Wv);
    k_pmat<<<32, 256>>>(Wo);
    k_gemm_tc<512, 2><<<dim3(1, 512), 512, SM_TC_TOTAL>>>(
        (const __nv_bfloat16*)p_swh, (const __nv_bfloat16*)p_swl,
        (const __nv_bfloat16*)p_ph, (const __nv_bfloat16*)p_pl, bo, out);
}